// round 5
// baseline (speedup 1.0000x reference)
#include <cuda_runtime.h>
#include <math.h>
#include <stdint.h>

#define BB   4
#define TT   32768
#define BT   (BB*TT)           // 131072 points
#define QQ   8192
#define HH   128
#define RR   64
#define RR2  4096
#define CDIM 512

// ---------------- scratch (static device memory; no allocations) ----------------
__device__ float    g_X  [BT*256];            // [NET | pooled] concat buffer (tf32-rounded)
__device__ float    g_H  [BT*128];            // hidden (relu'd + tf32-rounded)
__device__ float    g_NT [BT*128];            // shortcut temp (fp32)
__device__ float    g_C  [BT*CDIM];           // fc_c output (fp32)
__device__ unsigned g_MAX[3*BB*RR2*128];      // per-plane max pool
__device__ float    g_FEA[3*BB*RR2*CDIM];     // per-plane mean feat
__device__ float    g_CNT[3*BB*RR2];          // per-plane counts
__device__ float    g_INV[3*BB*RR2];          // per-plane 1/max(count,1)
__device__ int      g_IDX[3*BT];              // per-plane cell index
__device__ float    g_WP [475136];            // tf32-preconverted + col-permuted weights

// offsets into g_WP
#define WP_W0 0                               // 5*256*128 = 163840
#define WP_W1 163840                          // 5*128*128 =  81920
#define WP_WS 245760                          // 5*256*128 = 163840
#define WP_FC 409600                          // 128*512   =  65536

// ---------------- helpers ----------------
__device__ __forceinline__ unsigned f2o(float f) {
    unsigned b = __float_as_uint(f);
    return (b & 0x80000000u) ? ~b : (b | 0x80000000u);
}
__device__ __forceinline__ float o2f(unsigned o) {
    return __uint_as_float((o & 0x80000000u) ? (o ^ 0x80000000u) : ~o);
}
__device__ __forceinline__ float nrmc(float v) {
    v = v * (1.0f / 1.1f) + 0.5f;
    return fminf(fmaxf(v, 0.0f), 1.0f - 1e-6f);
}
__device__ __forceinline__ uint32_t to_tf32(float x) {
    uint32_t u;
    asm("cvt.rna.tf32.f32 %0, %1;" : "=r"(u) : "f"(x));
    return u;
}
__device__ __forceinline__ float rnd_tf32(float x) {
    return __uint_as_float(to_tf32(x));
}
__device__ __forceinline__ void mma_tf32(float c[4], const uint32_t a[4], const uint32_t b[2]) {
    asm volatile(
        "mma.sync.aligned.m16n8k8.row.col.f32.tf32.tf32.f32 "
        "{%0,%1,%2,%3}, {%4,%5,%6,%7}, {%8,%9}, {%0,%1,%2,%3};"
        : "+f"(c[0]), "+f"(c[1]), "+f"(c[2]), "+f"(c[3])
        : "r"(a[0]), "r"(a[1]), "r"(a[2]), "r"(a[3]), "r"(b[0]), "r"(b[1]));
}
__device__ __forceinline__ void cp16(uint32_t s, const float* g) {
    asm volatile("cp.async.cg.shared.global [%0], [%1], 16;" :: "r"(s), "l"(g));
}
__device__ __forceinline__ void cp_commit() { asm volatile("cp.async.commit_group;"); }
__device__ __forceinline__ void cp_wait0()  { asm volatile("cp.async.wait_group 0;"); }

// ---------------- weight prep: tf32 round + column permutation (ONE launch) ----------------
// permutation within each 128-col tile half-of-64: phys = ((n&7)<<3)|((n&63)>>3), keep bit 64
__global__ void k_cvtw_all(const float* __restrict__ w0, const float* __restrict__ w1,
                           const float* __restrict__ ws, const float* __restrict__ fc,
                           float* __restrict__ WP) {
    int i = blockIdx.x * 256 + threadIdx.x;
    const float* src; int Nout, base, off;
    if      (i < 163840) { src = w0; base = WP_W0; off = i;          Nout = 128; }
    else if (i < 245760) { src = w1; base = WP_W1; off = i - 163840; Nout = 128; }
    else if (i < 409600) { src = ws; base = WP_WS; off = i - 245760; Nout = 128; }
    else if (i < 475136) { src = fc; base = WP_FC; off = i - 409600; Nout = 512; }
    else return;
    int k = off / Nout, n = off % Nout;
    int pn = (n & ~63) | ((n & 7) << 3) | ((n & 63) >> 3);
    WP[base + k * Nout + pn] = rnd_tf32(src[off]);
}

// ---------------- index computation + counts ----------------
__global__ void k_index(const float* __restrict__ p) {
    int t = blockIdx.x * 256 + threadIdx.x;
    if (t >= BT) return;
    float x = p[t*3+0], y = p[t*3+1], z = p[t*3+2];
    int b = t >> 15;
    int gx, gy, cell;
    gx = (int)floorf(nrmc(x) * RR); gy = (int)floorf(nrmc(z) * RR);
    cell = gx + RR*gy; g_IDX[0*BT + t] = cell;
    atomicAdd(&g_CNT[(0*BB + b)*RR2 + cell], 1.0f);
    gx = (int)floorf(nrmc(x) * RR); gy = (int)floorf(nrmc(y) * RR);
    cell = gx + RR*gy; g_IDX[1*BT + t] = cell;
    atomicAdd(&g_CNT[(1*BB + b)*RR2 + cell], 1.0f);
    gx = (int)floorf(nrmc(y) * RR); gy = (int)floorf(nrmc(z) * RR);
    cell = gx + RR*gy; g_IDX[2*BT + t] = cell;
    atomicAdd(&g_CNT[(2*BB + b)*RR2 + cell], 1.0f);
}

// ---------------- inverse counts ----------------
__global__ void k_inv() {
    int i = blockIdx.x * 256 + threadIdx.x;
    if (i < 3*BB*RR2) g_INV[i] = 1.0f / fmaxf(g_CNT[i], 1.0f);
}

// ---------------- fc_pos: X0 = round(p @ W(3,256) + b) ----------------
__global__ void k_pos(const float* __restrict__ p, const float* __restrict__ w,
                      const float* __restrict__ b) {
    int gi = blockIdx.x * 256 + threadIdx.x;   // BT*256 threads
    int t = gi >> 8, j = gi & 255;
    float p0 = p[t*3+0], p1 = p[t*3+1], p2 = p[t*3+2];
    g_X[gi] = rnd_tf32(p0 * w[j] + p1 * w[256 + j] + p2 * w[512 + j] + b[j]);
}

// ---------------- TF32 tensor-core GEMM, cp.async 2-stage pipeline ----------------
// C = act(A) @ W + bias [+ D]; W pre-converted tf32 AND column-permuted;
// A pre-rounded tf32 in memory. Optional output relu / tf32-round.
#define AS_STRIDE 36
#define BS_STRIDE 136
#define AS_FLOATS (128*AS_STRIDE)   // 4608
#define BS_FLOATS (32*BS_STRIDE)    // 4352
#define SMEM_BYTES ((2*AS_FLOATS + 2*BS_FLOATS) * 4)   // 71680

template<int K, bool RELU, bool BIAS, bool ACCD, bool ORELU, bool OCVT>
__global__ void __launch_bounds__(256, 2)
k_tgemm(const float* __restrict__ A, int ASt,
        const float* __restrict__ W, int Nout,
        const float* __restrict__ bias,
        const float* __restrict__ D, int DS,
        float* __restrict__ Cm, int CS) {
    extern __shared__ float smem[];
    float* AsB[2] = { smem, smem + AS_FLOATS };
    float* BsB[2] = { smem + 2*AS_FLOATS, smem + 2*AS_FLOATS + BS_FLOATS };

    int tid  = threadIdx.x;
    int wid  = tid >> 5, lane = tid & 31;
    int gid  = lane >> 2, tig = lane & 3;
    int wm   = (wid >> 1) * 32;
    int wn   = (wid & 1) * 64;
    int row0 = blockIdx.y * 128;
    int col0 = blockIdx.x * 128;

    uint32_t sA[2], sB[2];
    sA[0] = (uint32_t)__cvta_generic_to_shared(AsB[0]);
    sA[1] = (uint32_t)__cvta_generic_to_shared(AsB[1]);
    sB[0] = (uint32_t)__cvta_generic_to_shared(BsB[0]);
    sB[1] = (uint32_t)__cvta_generic_to_shared(BsB[1]);

    float acc[2][8][4];
#pragma unroll
    for (int mf = 0; mf < 2; mf++)
#pragma unroll
        for (int nf = 0; nf < 8; nf++)
#pragma unroll
            for (int i = 0; i < 4; i++) acc[mf][nf][i] = 0.0f;

    auto prefetch = [&](int k0, int s) {
#pragma unroll
        for (int i = 0; i < 4; i++) {          // A tile 128x32
            int chunk = i * 256 + tid;
            int r  = chunk >> 3;
            int c4 = chunk & 7;
            cp16(sA[s] + (r * AS_STRIDE + c4 * 4) * 4,
                 &A[(size_t)(row0 + r) * ASt + k0 + c4 * 4]);
        }
#pragma unroll
        for (int i = 0; i < 4; i++) {          // B tile 32x128 (permuted cols)
            int chunk = i * 256 + tid;
            int kr  = chunk >> 5;
            int nc4 = chunk & 31;
            cp16(sB[s] + (kr * BS_STRIDE + nc4 * 4) * 4,
                 &W[(size_t)(k0 + kr) * Nout + col0 + nc4 * 4]);
        }
        cp_commit();
    };

    constexpr int NK = K / 32;
    prefetch(0, 0);

#pragma unroll
    for (int kt = 0; kt < NK; kt++) {
        int cur = kt & 1;
        cp_wait0();
        __syncthreads();
        if (kt + 1 < NK) prefetch((kt + 1) * 32, cur ^ 1);

        const float* as = AsB[cur];
        const float* bs = BsB[cur];
#pragma unroll
        for (int kk = 0; kk < 32; kk += 8) {
            uint32_t af[2][4];
#pragma unroll
            for (int mf = 0; mf < 2; mf++) {
                int r = wm + mf * 16;
                float a0 = as[(r + gid    ) * AS_STRIDE + kk + tig    ];
                float a1 = as[(r + gid + 8) * AS_STRIDE + kk + tig    ];
                float a2 = as[(r + gid    ) * AS_STRIDE + kk + tig + 4];
                float a3 = as[(r + gid + 8) * AS_STRIDE + kk + tig + 4];
                if (RELU) {
                    a0 = fmaxf(a0, 0.0f); a1 = fmaxf(a1, 0.0f);
                    a2 = fmaxf(a2, 0.0f); a3 = fmaxf(a3, 0.0f);
                }
                af[mf][0] = __float_as_uint(a0);
                af[mf][1] = __float_as_uint(a1);
                af[mf][2] = __float_as_uint(a2);
                af[mf][3] = __float_as_uint(a3);
            }
            // B fragments: permuted storage -> phys (gid*8 + j) holds logical col j*8+gid
            uint32_t bf[8][2];
            const float* brow0 = &bs[(kk + tig    ) * BS_STRIDE + wn + gid * 8];
            const float* brow1 = &bs[(kk + tig + 4) * BS_STRIDE + wn + gid * 8];
            float4 q0 = *(const float4*)brow0;
            float4 q1 = *(const float4*)(brow0 + 4);
            float4 q2 = *(const float4*)brow1;
            float4 q3 = *(const float4*)(brow1 + 4);
            bf[0][0] = __float_as_uint(q0.x); bf[1][0] = __float_as_uint(q0.y);
            bf[2][0] = __float_as_uint(q0.z); bf[3][0] = __float_as_uint(q0.w);
            bf[4][0] = __float_as_uint(q1.x); bf[5][0] = __float_as_uint(q1.y);
            bf[6][0] = __float_as_uint(q1.z); bf[7][0] = __float_as_uint(q1.w);
            bf[0][1] = __float_as_uint(q2.x); bf[1][1] = __float_as_uint(q2.y);
            bf[2][1] = __float_as_uint(q2.z); bf[3][1] = __float_as_uint(q2.w);
            bf[4][1] = __float_as_uint(q3.x); bf[5][1] = __float_as_uint(q3.y);
            bf[6][1] = __float_as_uint(q3.z); bf[7][1] = __float_as_uint(q3.w);
#pragma unroll
            for (int mf = 0; mf < 2; mf++)
#pragma unroll
                for (int nf = 0; nf < 8; nf++)
                    mma_tf32(acc[mf][nf], af[mf], bf[nf]);
        }
        __syncthreads();
    }

    // --- epilogue (logical columns; output NOT permuted) ---
#pragma unroll
    for (int mf = 0; mf < 2; mf++) {
        int r0 = row0 + wm + mf * 16 + gid;
#pragma unroll
        for (int nf = 0; nf < 8; nf++) {
            int c = col0 + wn + nf * 8 + 2 * tig;
            float v0 = acc[mf][nf][0], v1 = acc[mf][nf][1];
            float v2 = acc[mf][nf][2], v3 = acc[mf][nf][3];
            if (BIAS) {
                float b0 = bias[c], b1 = bias[c + 1];
                v0 += b0; v1 += b1; v2 += b0; v3 += b1;
            }
            if (ACCD) {
                float2 d0 = *(const float2*)&D[(size_t)r0 * DS + c];
                float2 d1 = *(const float2*)&D[(size_t)(r0 + 8) * DS + c];
                v0 += d0.x; v1 += d0.y; v2 += d1.x; v3 += d1.y;
            }
            if (ORELU) {
                v0 = fmaxf(v0, 0.0f); v1 = fmaxf(v1, 0.0f);
                v2 = fmaxf(v2, 0.0f); v3 = fmaxf(v3, 0.0f);
            }
            if (OCVT) {
                v0 = rnd_tf32(v0); v1 = rnd_tf32(v1);
                v2 = rnd_tf32(v2); v3 = rnd_tf32(v3);
            }
            float2 s0; s0.x = v0; s0.y = v1;
            float2 s1; s1.x = v2; s1.y = v3;
            *(float2*)&Cm[(size_t)r0 * CS + c] = s0;
            *(float2*)&Cm[(size_t)(r0 + 8) * CS + c] = s1;
        }
    }
}

// ---------------- zeroing ----------------
__global__ void k_zero_u(unsigned* ptr, int n) {
    for (int i = blockIdx.x * 256 + threadIdx.x; i < n; i += gridDim.x * 256) ptr[i] = 0u;
}
__global__ void k_zero_f(float* ptr, int n) {
    for (int i = blockIdx.x * 256 + threadIdx.x; i < n; i += gridDim.x * 256) ptr[i] = 0.0f;
}

// ---------------- scatter max (NET lives in g_X[:, :128]) ----------------
__global__ void k_scatter_max() {
    int gi = blockIdx.x * 256 + threadIdx.x;   // BT*32 threads
    int t = gi >> 5, c4 = (gi & 31) * 4;
    int b = t >> 15;
    float4 v = *(const float4*)&g_X[(size_t)t * 256 + c4];
    unsigned o0 = f2o(v.x), o1 = f2o(v.y), o2 = f2o(v.z), o3 = f2o(v.w);
#pragma unroll
    for (int pl = 0; pl < 3; pl++) {
        int cell = g_IDX[pl * BT + t];
        unsigned* m = &g_MAX[(size_t)((pl * BB + b) * RR2 + cell) * 128 + c4];
        atomicMax(m + 0, o0); atomicMax(m + 1, o1);
        atomicMax(m + 2, o2); atomicMax(m + 3, o3);
    }
}

// ---------------- gather pooled into g_X[:, 128:256] (tf32-rounded) ----------------
__global__ void k_gather() {
    int gi = blockIdx.x * 256 + threadIdx.x;   // BT*32 threads
    int t = gi >> 5, c4 = (gi & 31) * 4;
    int b = t >> 15;
    float4 s; s.x = 0.0f; s.y = 0.0f; s.z = 0.0f; s.w = 0.0f;
#pragma unroll
    for (int pl = 0; pl < 3; pl++) {
        int cell = g_IDX[pl * BT + t];
        const unsigned* m = &g_MAX[(size_t)((pl * BB + b) * RR2 + cell) * 128 + c4];
        s.x += o2f(m[0]); s.y += o2f(m[1]); s.z += o2f(m[2]); s.w += o2f(m[3]);
    }
    s.x = rnd_tf32(s.x); s.y = rnd_tf32(s.y);
    s.z = rnd_tf32(s.z); s.w = rnd_tf32(s.w);
    *(float4*)&g_X[(size_t)t * 256 + 128 + c4] = s;
}

// ---------------- scatter mean: pre-scaled adds (FEA holds means directly) ----------------
__global__ void k_scatter_add() {
    int gi = blockIdx.x * 256 + threadIdx.x;   // BT*128 threads
    int t = gi >> 7, c4 = (gi & 127) * 4;
    int b = t >> 15;
    float4 v = *(const float4*)&g_C[(size_t)t * CDIM + c4];
#pragma unroll
    for (int pl = 0; pl < 3; pl++) {
        int cell = g_IDX[pl * BT + t];
        float inv = g_INV[(pl * BB + b) * RR2 + cell];
        float* f = &g_FEA[(size_t)((pl * BB + b) * RR2 + cell) * CDIM + c4];
        asm volatile("red.global.add.v4.f32 [%0], {%1, %2, %3, %4};"
                     :: "l"(f), "f"(v.x * inv), "f"(v.y * inv),
                        "f"(v.z * inv), "f"(v.w * inv) : "memory");
    }
}

// ---------------- bilinear sample + sum over planes ----------------
__device__ __forceinline__ float4 samp4(int pl, float u, float v, int b, int c4) {
    float nu = nrmc(u), nv = nrmc(v);
    float gx = nu * (RR - 1), gy = nv * (RR - 1);
    float x0f = floorf(gx), y0f = floorf(gy);
    float wx = gx - x0f, wy = gy - y0f;
    int x0 = min(max((int)x0f, 0), RR - 1);
    int x1 = min(x0 + 1, RR - 1);
    int y0 = min(max((int)y0f, 0), RR - 1);
    int y1 = min(y0 + 1, RR - 1);
    const float* f = g_FEA + (size_t)((pl * BB + b) * RR2) * CDIM + c4;
    float4 f00 = *(const float4*)&f[(y0 * RR + x0) * CDIM];
    float4 f01 = *(const float4*)&f[(y0 * RR + x1) * CDIM];
    float4 f10 = *(const float4*)&f[(y1 * RR + x0) * CDIM];
    float4 f11 = *(const float4*)&f[(y1 * RR + x1) * CDIM];
    float w00 = (1.0f - wx) * (1.0f - wy), w01 = wx * (1.0f - wy);
    float w10 = (1.0f - wx) * wy,          w11 = wx * wy;
    float4 r;
    r.x = f00.x * w00 + f01.x * w01 + f10.x * w10 + f11.x * w11;
    r.y = f00.y * w00 + f01.y * w01 + f10.y * w10 + f11.y * w11;
    r.z = f00.z * w00 + f01.z * w01 + f10.z * w10 + f11.z * w11;
    r.w = f00.w * w00 + f01.w * w01 + f10.w * w10 + f11.w * w11;
    return r;
}

__global__ void k_sample(const float* __restrict__ query, float* __restrict__ out) {
    int gi = blockIdx.x * 256 + threadIdx.x;   // BB*QQ*128 threads
    int c4 = (gi & 127) * 4;
    int q  = gi >> 7;
    int b  = q >> 13;
    float qx = query[q*3+0], qy = query[q*3+1], qz = query[q*3+2];
    float4 a = samp4(0, qx, qz, b, c4);
    float4 s1 = samp4(1, qx, qy, b, c4);
    float4 s2 = samp4(2, qy, qz, b, c4);
    a.x += s1.x + s2.x; a.y += s1.y + s2.y;
    a.z += s1.z + s2.z; a.w += s1.w + s2.w;
    *(float4*)&out[(size_t)q * CDIM + c4] = a;
}

// ---------------- launch ----------------
extern "C" void kernel_launch(void* const* d_in, const int* in_sizes, int n_in,
                              void* d_out, int out_size) {
    const float* p        = (const float*)d_in[0];
    const float* query    = (const float*)d_in[1];
    const float* fc_pos_w = (const float*)d_in[2];
    const float* fc_pos_b = (const float*)d_in[3];
    const float* blk_w0   = (const float*)d_in[4];
    const float* blk_b0   = (const float*)d_in[5];
    const float* blk_w1   = (const float*)d_in[6];
    const float* blk_b1   = (const float*)d_in[7];
    const float* blk_ws   = (const float*)d_in[8];
    const float* fc_c_w   = (const float*)d_in[9];
    const float* fc_c_b   = (const float*)d_in[10];
    float* out = (float*)d_out;

    float *X, *H, *NT, *Cb, *FEA, *CNT, *WP;
    unsigned* MAXB;
    cudaGetSymbolAddress((void**)&X,    g_X);
    cudaGetSymbolAddress((void**)&H,    g_H);
    cudaGetSymbolAddress((void**)&NT,   g_NT);
    cudaGetSymbolAddress((void**)&Cb,   g_C);
    cudaGetSymbolAddress((void**)&FEA,  g_FEA);
    cudaGetSymbolAddress((void**)&CNT,  g_CNT);
    cudaGetSymbolAddress((void**)&WP,   g_WP);
    cudaGetSymbolAddress((void**)&MAXB, g_MAX);

    // GEMM variants:
    //  G1: H = relu(X)@w0+b0, out relu+cvt      <256, true,  true,  false, true,  true >
    //  G2: NT = X@ws (fp32 out)                 <256, false, false, false, false, false>
    //  G3: X[:, :128] = relu'dH@w1+b1+NT, cvt   <128, false, true,  true,  false, true >
    //  FC: C = NET@fc_w+fc_b (fp32 out)         <128, false, true,  false, false, false>
    cudaFuncSetAttribute(k_tgemm<256, true,  true,  false, true,  true >, cudaFuncAttributeMaxDynamicSharedMemorySize, SMEM_BYTES);
    cudaFuncSetAttribute(k_tgemm<256, false, false, false, false, false>, cudaFuncAttributeMaxDynamicSharedMemorySize, SMEM_BYTES);
    cudaFuncSetAttribute(k_tgemm<128, false, true,  true,  false, true >, cudaFuncAttributeMaxDynamicSharedMemorySize, SMEM_BYTES);
    cudaFuncSetAttribute(k_tgemm<128, false, true,  false, false, false>, cudaFuncAttributeMaxDynamicSharedMemorySize, SMEM_BYTES);

    k_cvtw_all<<<(475136 + 255) / 256, 256>>>(blk_w0, blk_w1, blk_ws, fc_c_w, WP);   // 0
    k_zero_f<<<48, 256>>>(CNT, 3*BB*RR2);                                            // 1
    k_index<<<BT/256, 256>>>(p);                                                     // 2
    k_inv<<<(3*BB*RR2 + 255)/256, 256>>>();                                          // 3
    k_pos<<<BT, 256>>>(p, fc_pos_w, fc_pos_b);                                       // 4

    dim3 g128(1, BT/128);
    dim3 g512(4, BT/128);

    for (int i = 0; i < 5; i++) {
        if (i > 0) {
            k_zero_u<<<2048, 256>>>(MAXB, 3*BB*RR2*128);
            k_scatter_max<<<BT*32/256, 256>>>();
            k_gather<<<BT*32/256, 256>>>();
        }
        const float* w0 = WP + WP_W0 + i*256*128;
        const float* b0 = blk_b0 + i*128;
        const float* w1 = WP + WP_W1 + i*128*128;
        const float* b1 = blk_b1 + i*128;
        const float* ws = WP + WP_WS + i*256*128;
        // H = relu_out(cvt(relu(X) @ w0 + b0))
        k_tgemm<256, true,  true,  false, true,  true ><<<g128, 256, SMEM_BYTES>>>(X, 256, w0, 128, b0, nullptr, 0, H, 128);   // launch 5 on i=0
        // NT = X @ ws
        k_tgemm<256, false, false, false, false, false><<<g128, 256, SMEM_BYTES>>>(X, 256, ws, 128, nullptr, nullptr, 0, NT, 128);
        // X[:, :128] = cvt(H_relu @ w1 + b1 + NT)
        k_tgemm<128, false, true,  true,  false, true ><<<g128, 256, SMEM_BYTES>>>(H, 128, w1, 128, b1, NT, 128, X, 256);
    }

    // c = NET @ fc_c_w + fc_c_b   (NET = X[:, :128], stride 256)
    k_tgemm<128, false, true, false, false, false><<<g512, 256, SMEM_BYTES>>>(X, 256, WP + WP_FC, 512, fc_c_b, nullptr, 0, Cb, 512);

    // scatter mean into plane grids (pre-scaled adds; FEA = means)
    k_zero_f<<<4096, 256>>>(FEA, 3*BB*RR2*CDIM);
    k_scatter_add<<<BT*128/256, 256>>>();

    // bilinear sample queries
    k_sample<<<BB*QQ*128/256, 256>>>(query, out);
}

// round 7
// speedup vs baseline: 1.0365x; 1.0365x over previous
#include <cuda_runtime.h>
#include <math.h>
#include <stdint.h>

#define BB   4
#define TT   32768
#define BT   (BB*TT)           // 131072 points
#define QQ   8192
#define HH   128
#define RR   64
#define RR2  4096
#define CDIM 512

// ---------------- scratch (static device memory; no allocations) ----------------
__device__ float    g_X  [BT*256];            // [NET | pooled] concat buffer (tf32-rounded)
__device__ float    g_H  [BT*128];            // hidden (relu'd + tf32-rounded)
__device__ float    g_NT [BT*128];            // shortcut temp (fp32)
__device__ float    g_C  [BT*CDIM];           // fc_c output (fp32)
__device__ unsigned g_MAX[3*BB*RR2*128];      // per-plane max pool
__device__ float    g_FEA[3*BB*RR2*CDIM];     // per-plane mean feat
__device__ float    g_CNT[3*BB*RR2];          // per-plane counts
__device__ float    g_INV[3*BB*RR2];          // per-plane 1/max(count,1)
__device__ int      g_IDX[3*BT];              // per-plane cell index
__device__ float    g_WP [475136];            // tf32 weights: WC | W1 | FC

// offsets into g_WP
#define WP_WC 0                               // 5*256*256 = 327680 ([w0|ws] concat)
#define WP_W1 327680                          // 5*128*128 =  81920
#define WP_FC 409600                          // 128*512   =  65536

// ---------------- helpers ----------------
__device__ __forceinline__ unsigned f2o(float f) {
    unsigned b = __float_as_uint(f);
    return (b & 0x80000000u) ? ~b : (b | 0x80000000u);
}
__device__ __forceinline__ float o2f(unsigned o) {
    return __uint_as_float((o & 0x80000000u) ? (o ^ 0x80000000u) : ~o);
}
__device__ __forceinline__ float nrmc(float v) {
    v = v * (1.0f / 1.1f) + 0.5f;
    return fminf(fmaxf(v, 0.0f), 1.0f - 1e-6f);
}
__device__ __forceinline__ uint32_t to_tf32(float x) {
    uint32_t u;
    asm("cvt.rna.tf32.f32 %0, %1;" : "=r"(u) : "f"(x));
    return u;
}
__device__ __forceinline__ float rnd_tf32(float x) {
    return __uint_as_float(to_tf32(x));
}
__device__ __forceinline__ void mma_tf32(float c[4], const uint32_t a[4], const uint32_t b[2]) {
    asm volatile(
        "mma.sync.aligned.m16n8k8.row.col.f32.tf32.tf32.f32 "
        "{%0,%1,%2,%3}, {%4,%5,%6,%7}, {%8,%9}, {%0,%1,%2,%3};"
        : "+f"(c[0]), "+f"(c[1]), "+f"(c[2]), "+f"(c[3])
        : "r"(a[0]), "r"(a[1]), "r"(a[2]), "r"(a[3]), "r"(b[0]), "r"(b[1]));
}
__device__ __forceinline__ void cp16(uint32_t s, const float* g) {
    asm volatile("cp.async.cg.shared.global [%0], [%1], 16;" :: "r"(s), "l"(g));
}
__device__ __forceinline__ void cp_commit() { asm volatile("cp.async.commit_group;"); }
__device__ __forceinline__ void cp_wait0()  { asm volatile("cp.async.wait_group 0;"); }

// ---------------- weight prep: tf32 round, build WC=[w0|ws] concat ----------------
__global__ void k_cvtw_all(const float* __restrict__ w0, const float* __restrict__ w1,
                           const float* __restrict__ ws, const float* __restrict__ fc,
                           float* __restrict__ WP) {
    int i = blockIdx.x * 256 + threadIdx.x;
    if (i < 327680) {                 // WC: blk 5 x (256k x 256n)
        int blk = i >> 16, rem = i & 65535;
        int k = rem >> 8, n = rem & 255;
        float v = (n < 128) ? w0[blk*32768 + k*128 + n]
                            : ws[blk*32768 + k*128 + (n - 128)];
        WP[i] = rnd_tf32(v);
    } else if (i < 409600) {          // W1
        WP[i] = rnd_tf32(w1[i - 327680]);
    } else if (i < 475136) {          // FC
        WP[i] = rnd_tf32(fc[i - 409600]);
    }
}

// ---------------- index computation + counts ----------------
__global__ void k_index(const float* __restrict__ p) {
    int t = blockIdx.x * 256 + threadIdx.x;
    if (t >= BT) return;
    float x = p[t*3+0], y = p[t*3+1], z = p[t*3+2];
    int b = t >> 15;
    int gx, gy, cell;
    gx = (int)floorf(nrmc(x) * RR); gy = (int)floorf(nrmc(z) * RR);
    cell = gx + RR*gy; g_IDX[0*BT + t] = cell;
    atomicAdd(&g_CNT[(0*BB + b)*RR2 + cell], 1.0f);
    gx = (int)floorf(nrmc(x) * RR); gy = (int)floorf(nrmc(y) * RR);
    cell = gx + RR*gy; g_IDX[1*BT + t] = cell;
    atomicAdd(&g_CNT[(1*BB + b)*RR2 + cell], 1.0f);
    gx = (int)floorf(nrmc(y) * RR); gy = (int)floorf(nrmc(z) * RR);
    cell = gx + RR*gy; g_IDX[2*BT + t] = cell;
    atomicAdd(&g_CNT[(2*BB + b)*RR2 + cell], 1.0f);
}

// ---------------- inverse counts ----------------
__global__ void k_inv() {
    int i = blockIdx.x * 256 + threadIdx.x;
    if (i < 3*BB*RR2) g_INV[i] = 1.0f / fmaxf(g_CNT[i], 1.0f);
}

// ---------------- fc_pos: X0 = round(p @ W(3,256) + b) ----------------
__global__ void k_pos(const float* __restrict__ p, const float* __restrict__ w,
                      const float* __restrict__ b) {
    int gi = blockIdx.x * 256 + threadIdx.x;   // BT*256 threads
    int t = gi >> 8, j = gi & 255;
    float p0 = p[t*3+0], p1 = p[t*3+1], p2 = p[t*3+2];
    g_X[gi] = rnd_tf32(p0 * w[j] + p1 * w[256 + j] + p2 * w[512 + j] + b[j]);
}

// ================= fused G1+G2: one 128x256 tile, A loaded ONCE =================
// H[:,0:128] = cvt(relu( relu(X)@w0 + b0 ))   (warps wn<128, relu'd A frags)
// NT[:,0:128] = X@ws                          (warps wn>=128, raw A frags)
// 512 threads, 16 warps (4m x 4n), warp tile 32x64, k-chunk 32, 2-stage cp.async.
#define AS_STRIDE   36
#define AS_FLOATS   (128*AS_STRIDE)            // 4608
#define B12_STRIDE  264
#define B12_FLOATS  (32*B12_STRIDE)            // 8448
#define SMEM12      ((2*AS_FLOATS + 2*B12_FLOATS) * 4)   // 104448 bytes

__global__ void __launch_bounds__(512, 1)
k_tgemm12(const float* __restrict__ A,          // X, stride 256
          const float* __restrict__ WC,         // 256x256 concat, tf32
          const float* __restrict__ b0,
          float* __restrict__ Hout,             // stride 128
          float* __restrict__ NTout) {          // stride 128
    extern __shared__ float smem[];
    float* AsB[2] = { smem, smem + AS_FLOATS };
    float* BsB[2] = { smem + 2*AS_FLOATS, smem + 2*AS_FLOATS + B12_FLOATS };

    int tid  = threadIdx.x;
    int wid  = tid >> 5, lane = tid & 31;
    int gid  = lane >> 2, tig = lane & 3;
    int wm   = (wid >> 2) * 32;      // 4 m-slots
    int wn   = (wid & 3) * 64;       // 4 n-slots over 256
    bool hpath = (wn < 128);
    int row0 = blockIdx.y * 128;

    uint32_t sA[2], sB[2];
    sA[0] = (uint32_t)__cvta_generic_to_shared(AsB[0]);
    sA[1] = (uint32_t)__cvta_generic_to_shared(AsB[1]);
    sB[0] = (uint32_t)__cvta_generic_to_shared(BsB[0]);
    sB[1] = (uint32_t)__cvta_generic_to_shared(BsB[1]);

    float acc[2][8][4];
#pragma unroll
    for (int mf = 0; mf < 2; mf++)
#pragma unroll
        for (int nf = 0; nf < 8; nf++)
#pragma unroll
            for (int i = 0; i < 4; i++) acc[mf][nf][i] = 0.0f;

    auto prefetch = [&](int k0, int s) {
#pragma unroll
        for (int i = 0; i < 2; i++) {          // A tile 128x32: 1024 chunks / 512 thr
            int chunk = i * 512 + tid;
            int r  = chunk >> 3;
            int c4 = chunk & 7;
            cp16(sA[s] + (r * AS_STRIDE + c4 * 4) * 4,
                 &A[(size_t)(row0 + r) * 256 + k0 + c4 * 4]);
        }
#pragma unroll
        for (int i = 0; i < 4; i++) {          // B tile 32x256: 2048 chunks
            int chunk = i * 512 + tid;
            int kr  = chunk >> 6;
            int nc4 = chunk & 63;
            cp16(sB[s] + (kr * B12_STRIDE + nc4 * 4) * 4,
                 &WC[(size_t)(k0 + kr) * 256 + nc4 * 4]);
        }
        cp_commit();
    };

    prefetch(0, 0);
#pragma unroll
    for (int kt = 0; kt < 8; kt++) {
        int cur = kt & 1;
        cp_wait0();
        __syncthreads();
        if (kt + 1 < 8) prefetch((kt + 1) * 32, cur ^ 1);

        const float* as = AsB[cur];
        const float* bs = BsB[cur];
#pragma unroll
        for (int kk = 0; kk < 32; kk += 8) {
            uint32_t af[2][4];
#pragma unroll
            for (int mf = 0; mf < 2; mf++) {
                int r = wm + mf * 16;
                float a0 = as[(r + gid    ) * AS_STRIDE + kk + tig    ];
                float a1 = as[(r + gid + 8) * AS_STRIDE + kk + tig    ];
                float a2 = as[(r + gid    ) * AS_STRIDE + kk + tig + 4];
                float a3 = as[(r + gid + 8) * AS_STRIDE + kk + tig + 4];
                if (hpath) {   // warp-uniform: H half uses relu(X)
                    a0 = fmaxf(a0, 0.0f); a1 = fmaxf(a1, 0.0f);
                    a2 = fmaxf(a2, 0.0f); a3 = fmaxf(a3, 0.0f);
                }
                af[mf][0] = __float_as_uint(a0);
                af[mf][1] = __float_as_uint(a1);
                af[mf][2] = __float_as_uint(a2);
                af[mf][3] = __float_as_uint(a3);
            }
            uint32_t bf[8][2];
#pragma unroll
            for (int nf = 0; nf < 8; nf++) {
                bf[nf][0] = __float_as_uint(bs[(kk + tig    ) * B12_STRIDE + wn + nf * 8 + gid]);
                bf[nf][1] = __float_as_uint(bs[(kk + tig + 4) * B12_STRIDE + wn + nf * 8 + gid]);
            }
#pragma unroll
            for (int mf = 0; mf < 2; mf++)
#pragma unroll
                for (int nf = 0; nf < 8; nf++)
                    mma_tf32(acc[mf][nf], af[mf], bf[nf]);
        }
        __syncthreads();
    }

    // epilogue: cols <128 -> H (bias+relu+cvt); cols >=128 -> NT (raw fp32)
#pragma unroll
    for (int mf = 0; mf < 2; mf++) {
        int r0 = row0 + wm + mf * 16 + gid;
#pragma unroll
        for (int nf = 0; nf < 8; nf++) {
            int c = wn + nf * 8 + 2 * tig;
            float v0 = acc[mf][nf][0], v1 = acc[mf][nf][1];
            float v2 = acc[mf][nf][2], v3 = acc[mf][nf][3];
            if (hpath) {
                float bb0 = b0[c], bb1 = b0[c + 1];
                v0 = rnd_tf32(fmaxf(v0 + bb0, 0.0f));
                v1 = rnd_tf32(fmaxf(v1 + bb1, 0.0f));
                v2 = rnd_tf32(fmaxf(v2 + bb0, 0.0f));
                v3 = rnd_tf32(fmaxf(v3 + bb1, 0.0f));
                float2 s0; s0.x = v0; s0.y = v1;
                float2 s1; s1.x = v2; s1.y = v3;
                *(float2*)&Hout[(size_t)r0 * 128 + c] = s0;
                *(float2*)&Hout[(size_t)(r0 + 8) * 128 + c] = s1;
            } else {
                int cn = c - 128;
                float2 s0; s0.x = v0; s0.y = v1;
                float2 s1; s1.x = v2; s1.y = v3;
                *(float2*)&NTout[(size_t)r0 * 128 + cn] = s0;
                *(float2*)&NTout[(size_t)(r0 + 8) * 128 + cn] = s1;
            }
        }
    }
}

// ================= generic 256-thread GEMM (G3, FC) =================
#define BS_STRIDE 136
#define BS_FLOATS (32*BS_STRIDE)    // 4352
#define SMEM_BYTES ((2*AS_FLOATS + 2*BS_FLOATS) * 4)   // 71680

template<int K, bool BIAS, bool ACCD, bool OCVT>
__global__ void __launch_bounds__(256, 2)
k_tgemm(const float* __restrict__ A, int ASt,
        const float* __restrict__ W, int Nout,
        const float* __restrict__ bias,
        const float* __restrict__ D, int DS,
        float* __restrict__ Cm, int CS) {
    extern __shared__ float smem[];
    float* AsB[2] = { smem, smem + AS_FLOATS };
    float* BsB[2] = { smem + 2*AS_FLOATS, smem + 2*AS_FLOATS + BS_FLOATS };

    int tid  = threadIdx.x;
    int wid  = tid >> 5, lane = tid & 31;
    int gid  = lane >> 2, tig = lane & 3;
    int wm   = (wid >> 1) * 32;
    int wn   = (wid & 1) * 64;
    int row0 = blockIdx.y * 128;
    int col0 = blockIdx.x * 128;

    uint32_t sA[2], sB[2];
    sA[0] = (uint32_t)__cvta_generic_to_shared(AsB[0]);
    sA[1] = (uint32_t)__cvta_generic_to_shared(AsB[1]);
    sB[0] = (uint32_t)__cvta_generic_to_shared(BsB[0]);
    sB[1] = (uint32_t)__cvta_generic_to_shared(BsB[1]);

    float acc[2][8][4];
#pragma unroll
    for (int mf = 0; mf < 2; mf++)
#pragma unroll
        for (int nf = 0; nf < 8; nf++)
#pragma unroll
            for (int i = 0; i < 4; i++) acc[mf][nf][i] = 0.0f;

    auto prefetch = [&](int k0, int s) {
#pragma unroll
        for (int i = 0; i < 4; i++) {
            int chunk = i * 256 + tid;
            int r  = chunk >> 3;
            int c4 = chunk & 7;
            cp16(sA[s] + (r * AS_STRIDE + c4 * 4) * 4,
                 &A[(size_t)(row0 + r) * ASt + k0 + c4 * 4]);
        }
#pragma unroll
        for (int i = 0; i < 4; i++) {
            int chunk = i * 256 + tid;
            int kr  = chunk >> 5;
            int nc4 = chunk & 31;
            cp16(sB[s] + (kr * BS_STRIDE + nc4 * 4) * 4,
                 &W[(size_t)(k0 + kr) * Nout + col0 + nc4 * 4]);
        }
        cp_commit();
    };

    constexpr int NK = K / 32;
    prefetch(0, 0);

#pragma unroll
    for (int kt = 0; kt < NK; kt++) {
        int cur = kt & 1;
        cp_wait0();
        __syncthreads();
        if (kt + 1 < NK) prefetch((kt + 1) * 32, cur ^ 1);

        const float* as = AsB[cur];
        const float* bs = BsB[cur];
#pragma unroll
        for (int kk = 0; kk < 32; kk += 8) {
            uint32_t af[2][4];
#pragma unroll
            for (int mf = 0; mf < 2; mf++) {
                int r = wm + mf * 16;
                af[mf][0] = __float_as_uint(as[(r + gid    ) * AS_STRIDE + kk + tig    ]);
                af[mf][1] = __float_as_uint(as[(r + gid + 8) * AS_STRIDE + kk + tig    ]);
                af[mf][2] = __float_as_uint(as[(r + gid    ) * AS_STRIDE + kk + tig + 4]);
                af[mf][3] = __float_as_uint(as[(r + gid + 8) * AS_STRIDE + kk + tig + 4]);
            }
            uint32_t bf[8][2];
#pragma unroll
            for (int nf = 0; nf < 8; nf++) {
                bf[nf][0] = __float_as_uint(bs[(kk + tig    ) * BS_STRIDE + wn + nf * 8 + gid]);
                bf[nf][1] = __float_as_uint(bs[(kk + tig + 4) * BS_STRIDE + wn + nf * 8 + gid]);
            }
#pragma unroll
            for (int mf = 0; mf < 2; mf++)
#pragma unroll
                for (int nf = 0; nf < 8; nf++)
                    mma_tf32(acc[mf][nf], af[mf], bf[nf]);
        }
        __syncthreads();
    }

#pragma unroll
    for (int mf = 0; mf < 2; mf++) {
        int r0 = row0 + wm + mf * 16 + gid;
#pragma unroll
        for (int nf = 0; nf < 8; nf++) {
            int c = col0 + wn + nf * 8 + 2 * tig;
            float v0 = acc[mf][nf][0], v1 = acc[mf][nf][1];
            float v2 = acc[mf][nf][2], v3 = acc[mf][nf][3];
            if (BIAS) {
                float b0 = bias[c], b1 = bias[c + 1];
                v0 += b0; v1 += b1; v2 += b0; v3 += b1;
            }
            if (ACCD) {
                float2 d0 = *(const float2*)&D[(size_t)r0 * DS + c];
                float2 d1 = *(const float2*)&D[(size_t)(r0 + 8) * DS + c];
                v0 += d0.x; v1 += d0.y; v2 += d1.x; v3 += d1.y;
            }
            if (OCVT) {
                v0 = rnd_tf32(v0); v1 = rnd_tf32(v1);
                v2 = rnd_tf32(v2); v3 = rnd_tf32(v3);
            }
            float2 s0; s0.x = v0; s0.y = v1;
            float2 s1; s1.x = v2; s1.y = v3;
            *(float2*)&Cm[(size_t)r0 * CS + c] = s0;
            *(float2*)&Cm[(size_t)(r0 + 8) * CS + c] = s1;
        }
    }
}

// ---------------- zeroing ----------------
__global__ void k_zero_u(unsigned* ptr, int n) {
    for (int i = blockIdx.x * 256 + threadIdx.x; i < n; i += gridDim.x * 256) ptr[i] = 0u;
}
__global__ void k_zero_f(float* ptr, int n) {
    for (int i = blockIdx.x * 256 + threadIdx.x; i < n; i += gridDim.x * 256) ptr[i] = 0.0f;
}

// ---------------- scatter max (NET lives in g_X[:, :128]) ----------------
__global__ void k_scatter_max() {
    int gi = blockIdx.x * 256 + threadIdx.x;   // BT*32 threads
    int t = gi >> 5, c4 = (gi & 31) * 4;
    int b = t >> 15;
    float4 v = *(const float4*)&g_X[(size_t)t * 256 + c4];
    unsigned o0 = f2o(v.x), o1 = f2o(v.y), o2 = f2o(v.z), o3 = f2o(v.w);
#pragma unroll
    for (int pl = 0; pl < 3; pl++) {
        int cell = g_IDX[pl * BT + t];
        unsigned* m = &g_MAX[(size_t)((pl * BB + b) * RR2 + cell) * 128 + c4];
        atomicMax(m + 0, o0); atomicMax(m + 1, o1);
        atomicMax(m + 2, o2); atomicMax(m + 3, o3);
    }
}

// ---------------- gather pooled into g_X[:, 128:256] (tf32-rounded) ----------------
__global__ void k_gather() {
    int gi = blockIdx.x * 256 + threadIdx.x;   // BT*32 threads
    int t = gi >> 5, c4 = (gi & 31) * 4;
    int b = t >> 15;
    float4 s; s.x = 0.0f; s.y = 0.0f; s.z = 0.0f; s.w = 0.0f;
#pragma unroll
    for (int pl = 0; pl < 3; pl++) {
        int cell = g_IDX[pl * BT + t];
        const unsigned* m = &g_MAX[(size_t)((pl * BB + b) * RR2 + cell) * 128 + c4];
        s.x += o2f(m[0]); s.y += o2f(m[1]); s.z += o2f(m[2]); s.w += o2f(m[3]);
    }
    s.x = rnd_tf32(s.x); s.y = rnd_tf32(s.y);
    s.z = rnd_tf32(s.z); s.w = rnd_tf32(s.w);
    *(float4*)&g_X[(size_t)t * 256 + 128 + c4] = s;
}

// ---------------- scatter mean: pre-scaled adds (FEA holds means) ----------------
__global__ void k_scatter_add() {
    int gi = blockIdx.x * 256 + threadIdx.x;   // BT*128 threads
    int t = gi >> 7, c4 = (gi & 127) * 4;
    int b = t >> 15;
    float4 v = *(const float4*)&g_C[(size_t)t * CDIM + c4];
#pragma unroll
    for (int pl = 0; pl < 3; pl++) {
        int cell = g_IDX[pl * BT + t];
        float inv = g_INV[(pl * BB + b) * RR2 + cell];
        float* f = &g_FEA[(size_t)((pl * BB + b) * RR2 + cell) * CDIM + c4];
        asm volatile("red.global.add.v4.f32 [%0], {%1, %2, %3, %4};"
                     :: "l"(f), "f"(v.x * inv), "f"(v.y * inv),
                        "f"(v.z * inv), "f"(v.w * inv) : "memory");
    }
}

// ---------------- bilinear sample + sum over planes ----------------
__device__ __forceinline__ float4 samp4(int pl, float u, float v, int b, int c4) {
    float nu = nrmc(u), nv = nrmc(v);
    float gx = nu * (RR - 1), gy = nv * (RR - 1);
    float x0f = floorf(gx), y0f = floorf(gy);
    float wx = gx - x0f, wy = gy - y0f;
    int x0 = min(max((int)x0f, 0), RR - 1);
    int x1 = min(x0 + 1, RR - 1);
    int y0 = min(max((int)y0f, 0), RR - 1);
    int y1 = min(y0 + 1, RR - 1);
    const float* f = g_FEA + (size_t)((pl * BB + b) * RR2) * CDIM + c4;
    float4 f00 = *(const float4*)&f[(y0 * RR + x0) * CDIM];
    float4 f01 = *(const float4*)&f[(y0 * RR + x1) * CDIM];
    float4 f10 = *(const float4*)&f[(y1 * RR + x0) * CDIM];
    float4 f11 = *(const float4*)&f[(y1 * RR + x1) * CDIM];
    float w00 = (1.0f - wx) * (1.0f - wy), w01 = wx * (1.0f - wy);
    float w10 = (1.0f - wx) * wy,          w11 = wx * wy;
    float4 r;
    r.x = f00.x * w00 + f01.x * w01 + f10.x * w10 + f11.x * w11;
    r.y = f00.y * w00 + f01.y * w01 + f10.y * w10 + f11.y * w11;
    r.z = f00.z * w00 + f01.z * w01 + f10.z * w10 + f11.z * w11;
    r.w = f00.w * w00 + f01.w * w01 + f10.w * w10 + f11.w * w11;
    return r;
}

__global__ void k_sample(const float* __restrict__ query, float* __restrict__ out) {
    int gi = blockIdx.x * 256 + threadIdx.x;   // BB*QQ*128 threads
    int c4 = (gi & 127) * 4;
    int q  = gi >> 7;
    int b  = q >> 13;
    float qx = query[q*3+0], qy = query[q*3+1], qz = query[q*3+2];
    float4 a = samp4(0, qx, qz, b, c4);
    float4 s1 = samp4(1, qx, qy, b, c4);
    float4 s2 = samp4(2, qy, qz, b, c4);
    a.x += s1.x + s2.x; a.y += s1.y + s2.y;
    a.z += s1.z + s2.z; a.w += s1.w + s2.w;
    *(float4*)&out[(size_t)q * CDIM + c4] = a;
}

// ---------------- launch ----------------
extern "C" void kernel_launch(void* const* d_in, const int* in_sizes, int n_in,
                              void* d_out, int out_size) {
    const float* p        = (const float*)d_in[0];
    const float* query    = (const float*)d_in[1];
    const float* fc_pos_w = (const float*)d_in[2];
    const float* fc_pos_b = (const float*)d_in[3];
    const float* blk_w0   = (const float*)d_in[4];
    const float* blk_b0   = (const float*)d_in[5];
    const float* blk_w1   = (const float*)d_in[6];
    const float* blk_b1   = (const float*)d_in[7];
    const float* blk_ws   = (const float*)d_in[8];
    const float* fc_c_w   = (const float*)d_in[9];
    const float* fc_c_b   = (const float*)d_in[10];
    float* out = (float*)d_out;

    float *X, *H, *NT, *Cb, *FEA, *CNT, *WP;
    unsigned* MAXB;
    cudaGetSymbolAddress((void**)&X,    g_X);
    cudaGetSymbolAddress((void**)&H,    g_H);
    cudaGetSymbolAddress((void**)&NT,   g_NT);
    cudaGetSymbolAddress((void**)&Cb,   g_C);
    cudaGetSymbolAddress((void**)&FEA,  g_FEA);
    cudaGetSymbolAddress((void**)&CNT,  g_CNT);
    cudaGetSymbolAddress((void**)&WP,   g_WP);
    cudaGetSymbolAddress((void**)&MAXB, g_MAX);

    cudaFuncSetAttribute(k_tgemm12, cudaFuncAttributeMaxDynamicSharedMemorySize, SMEM12);
    cudaFuncSetAttribute(k_tgemm<128, true,  true,  true >, cudaFuncAttributeMaxDynamicSharedMemorySize, SMEM_BYTES);
    cudaFuncSetAttribute(k_tgemm<128, true,  false, false>, cudaFuncAttributeMaxDynamicSharedMemorySize, SMEM_BYTES);

    k_cvtw_all<<<(475136 + 255) / 256, 256>>>(blk_w0, blk_w1, blk_ws, fc_c_w, WP);   // 0
    k_zero_f<<<48, 256>>>(CNT, 3*BB*RR2);                                            // 1
    k_index<<<BT/256, 256>>>(p);                                                     // 2
    k_inv<<<(3*BB*RR2 + 255)/256, 256>>>();                                          // 3
    k_pos<<<BT, 256>>>(p, fc_pos_w, fc_pos_b);                                       // 4

    dim3 g12(1, BT/128);
    dim3 g128(1, BT/128);
    dim3 g512(4, BT/128);

    for (int i = 0; i < 5; i++) {
        if (i > 0) {
            k_zero_u<<<2048, 256>>>(MAXB, 3*BB*RR2*128);
            k_scatter_max<<<BT*32/256, 256>>>();
            k_gather<<<BT*32/256, 256>>>();
        }
        const float* wc = WP + WP_WC + i*256*256;
        const float* b0 = blk_b0 + i*128;
        const float* w1 = WP + WP_W1 + i*128*128;
        const float* b1 = blk_b1 + i*128;
        // fused: H = cvt(relu(relu(X)@w0+b0)); NT = X@ws     (launch 5 on i=0)
        k_tgemm12<<<g12, 512, SMEM12>>>(X, wc, b0, H, NT);
        // X[:, :128] = cvt(H @ w1 + b1 + NT)
        k_tgemm<128, true, true, true><<<g128, 256, SMEM_BYTES>>>(H, 128, w1, 128, b1, NT, 128, X, 256);
    }

    // c = NET @ fc_c_w + fc_c_b   (NET = X[:, :128], stride 256)
    k_tgemm<128, true, false, false><<<g512, 256, SMEM_BYTES>>>(X, 256, WP + WP_FC, 512, fc_c_b, nullptr, 0, Cb, 512);

    // scatter mean into plane grids (pre-scaled adds; FEA = means)
    k_zero_f<<<4096, 256>>>(FEA, 3*BB*RR2*CDIM);
    k_scatter_add<<<BT*128/256, 256>>>();

    // bilinear sample queries
    k_sample<<<BB*QQ*128/256, 256>>>(query, out);
}

// round 8
// speedup vs baseline: 1.1498x; 1.1093x over previous
#include <cuda_runtime.h>
#include <math.h>
#include <stdint.h>

#define BB   4
#define TT   32768
#define BT   (BB*TT)           // 131072 points
#define QQ   8192
#define HH   128
#define RR   64
#define RR2  4096
#define CDIM 512

// ---------------- scratch (static device memory; no allocations) ----------------
__device__ float    g_X  [BT*256];            // X0 = fc_pos output (tf32-rounded), 256-wide
__device__ float    g_NET[BT*128];            // block output NET (tf32-rounded), stride 128
__device__ float    g_H  [BT*128];            // hidden (relu'd + tf32-rounded)
__device__ float    g_NT [BT*128];            // shortcut temp (fp32)
__device__ float    g_C  [BT*CDIM];           // fc_c output (fp32)
__device__ unsigned g_MAX[3*BB*RR2*128];      // per-plane max pool
__device__ float    g_FEA[3*BB*RR2*CDIM];     // per-plane mean feat
__device__ float    g_CNT[3*BB*RR2];          // per-plane counts
__device__ float    g_INV[3*BB*RR2];          // per-plane 1/max(count,1)
__device__ int      g_IDX[3*BT];              // per-plane cell index
__device__ float    g_WP [475136];            // tf32 weights: WC | W1 | FC

#define WP_WC 0                               // 5*256*256 = 327680 ([w0|ws] concat)
#define WP_W1 327680                          // 5*128*128 =  81920
#define WP_FC 409600                          // 128*512   =  65536

// ---------------- helpers ----------------
__device__ __forceinline__ unsigned f2o(float f) {
    unsigned b = __float_as_uint(f);
    return (b & 0x80000000u) ? ~b : (b | 0x80000000u);
}
__device__ __forceinline__ float o2f(unsigned o) {
    return __uint_as_float((o & 0x80000000u) ? (o ^ 0x80000000u) : ~o);
}
__device__ __forceinline__ float nrmc(float v) {
    v = v * (1.0f / 1.1f) + 0.5f;
    return fminf(fmaxf(v, 0.0f), 1.0f - 1e-6f);
}
__device__ __forceinline__ uint32_t to_tf32(float x) {
    uint32_t u;
    asm("cvt.rna.tf32.f32 %0, %1;" : "=r"(u) : "f"(x));
    return u;
}
__device__ __forceinline__ float rnd_tf32(float x) {
    return __uint_as_float(to_tf32(x));
}
__device__ __forceinline__ void mma_tf32(float c[4], const uint32_t a[4], const uint32_t b[2]) {
    asm volatile(
        "mma.sync.aligned.m16n8k8.row.col.f32.tf32.tf32.f32 "
        "{%0,%1,%2,%3}, {%4,%5,%6,%7}, {%8,%9}, {%0,%1,%2,%3};"
        : "+f"(c[0]), "+f"(c[1]), "+f"(c[2]), "+f"(c[3])
        : "r"(a[0]), "r"(a[1]), "r"(a[2]), "r"(a[3]), "r"(b[0]), "r"(b[1]));
}
__device__ __forceinline__ void cp16(uint32_t s, const float* g) {
    asm volatile("cp.async.cg.shared.global [%0], [%1], 16;" :: "r"(s), "l"(g));
}
__device__ __forceinline__ void cp_commit() { asm volatile("cp.async.commit_group;"); }
__device__ __forceinline__ void cp_wait0()  { asm volatile("cp.async.wait_group 0;"); }
__device__ __forceinline__ void redmax_u32(unsigned* p, unsigned v) {
    asm volatile("red.global.max.u32 [%0], %1;" :: "l"(p), "r"(v) : "memory");
}

// ---------------- weight prep: tf32 round, build WC=[w0|ws] concat ----------------
__global__ void k_cvtw_all(const float* __restrict__ w0, const float* __restrict__ w1,
                           const float* __restrict__ ws, const float* __restrict__ fc,
                           float* __restrict__ WP) {
    int i = blockIdx.x * 256 + threadIdx.x;
    if (i < 327680) {                 // WC: blk 5 x (256k x 256n)
        int blk = i >> 16, rem = i & 65535;
        int k = rem >> 8, n = rem & 255;
        float v = (n < 128) ? w0[blk*32768 + k*128 + n]
                            : ws[blk*32768 + k*128 + (n - 128)];
        WP[i] = rnd_tf32(v);
    } else if (i < 409600) {          // W1
        WP[i] = rnd_tf32(w1[i - 327680]);
    } else if (i < 475136) {          // FC
        WP[i] = rnd_tf32(fc[i - 409600]);
    }
}

// ---------------- index computation + counts ----------------
__global__ void k_index(const float* __restrict__ p) {
    int t = blockIdx.x * 256 + threadIdx.x;
    if (t >= BT) return;
    float x = p[t*3+0], y = p[t*3+1], z = p[t*3+2];
    int b = t >> 15;
    int gx, gy, cell;
    gx = (int)floorf(nrmc(x) * RR); gy = (int)floorf(nrmc(z) * RR);
    cell = gx + RR*gy; g_IDX[0*BT + t] = cell;
    atomicAdd(&g_CNT[(0*BB + b)*RR2 + cell], 1.0f);
    gx = (int)floorf(nrmc(x) * RR); gy = (int)floorf(nrmc(y) * RR);
    cell = gx + RR*gy; g_IDX[1*BT + t] = cell;
    atomicAdd(&g_CNT[(1*BB + b)*RR2 + cell], 1.0f);
    gx = (int)floorf(nrmc(y) * RR); gy = (int)floorf(nrmc(z) * RR);
    cell = gx + RR*gy; g_IDX[2*BT + t] = cell;
    atomicAdd(&g_CNT[(2*BB + b)*RR2 + cell], 1.0f);
}

// ---------------- inverse counts ----------------
__global__ void k_inv() {
    int i = blockIdx.x * 256 + threadIdx.x;
    if (i < 3*BB*RR2) g_INV[i] = 1.0f / fmaxf(g_CNT[i], 1.0f);
}

// ---------------- fc_pos: X0 = round(p @ W(3,256) + b) ----------------
__global__ void k_pos(const float* __restrict__ p, const float* __restrict__ w,
                      const float* __restrict__ b) {
    int gi = blockIdx.x * 256 + threadIdx.x;   // BT*256 threads
    int t = gi >> 8, j = gi & 255;
    float p0 = p[t*3+0], p1 = p[t*3+1], p2 = p[t*3+2];
    g_X[gi] = rnd_tf32(p0 * w[j] + p1 * w[256 + j] + p2 * w[512 + j] + b[j]);
}

// ================= fused G1+G2 (+ in-prefetch pooled gather) =================
// A logical = [NET | pooled] (POOLED) or X0 256-wide (!POOLED).
// H = cvt(relu(relu(A)@w0 + b0)); NT = A@ws.
// 512 threads, 16 warps (4m x 4n), warp tile 32x64, k-chunk 32, 2-stage cp.async.
#define AS_STRIDE   36
#define AS_FLOATS   (128*AS_STRIDE)            // 4608
#define B12_STRIDE  264
#define B12_FLOATS  (32*B12_STRIDE)            // 8448
#define SMEM12      ((2*AS_FLOATS + 2*B12_FLOATS) * 4)   // 104448 bytes

template<bool POOLED>
__global__ void __launch_bounds__(512, 1)
k_tgemm12(const float* __restrict__ A,          // NET (stride 128) or X0 (stride 256)
          const float* __restrict__ WC,         // 256x256 concat, tf32
          const float* __restrict__ b0,
          float* __restrict__ Hout,             // stride 128
          float* __restrict__ NTout) {          // stride 128
    extern __shared__ float smem[];
    float* AsB[2] = { smem, smem + AS_FLOATS };
    float* BsB[2] = { smem + 2*AS_FLOATS, smem + 2*AS_FLOATS + B12_FLOATS };

    int tid  = threadIdx.x;
    int wid  = tid >> 5, lane = tid & 31;
    int gid  = lane >> 2, tig = lane & 3;
    int wm   = (wid >> 2) * 32;
    int wn   = (wid & 3) * 64;
    bool hpath = (wn < 128);
    int row0 = blockIdx.y * 128;

    uint32_t sA[2], sB[2];
    sA[0] = (uint32_t)__cvta_generic_to_shared(AsB[0]);
    sA[1] = (uint32_t)__cvta_generic_to_shared(AsB[1]);
    sB[0] = (uint32_t)__cvta_generic_to_shared(BsB[0]);
    sB[1] = (uint32_t)__cvta_generic_to_shared(BsB[1]);

    float acc[2][8][4];
#pragma unroll
    for (int mf = 0; mf < 2; mf++)
#pragma unroll
        for (int nf = 0; nf < 8; nf++)
#pragma unroll
            for (int i = 0; i < 4; i++) acc[mf][nf][i] = 0.0f;

    auto prefetch = [&](int k0, int s) {
        if (!POOLED) {
#pragma unroll
            for (int i = 0; i < 2; i++) {      // A tile 128x32 from X0 (stride 256)
                int chunk = i * 512 + tid;
                int r  = chunk >> 3;
                int c4 = chunk & 7;
                cp16(sA[s] + (r * AS_STRIDE + c4 * 4) * 4,
                     &A[(size_t)(row0 + r) * 256 + k0 + c4 * 4]);
            }
        } else if (k0 < 128) {
#pragma unroll
            for (int i = 0; i < 2; i++) {      // A tile from NET (stride 128)
                int chunk = i * 512 + tid;
                int r  = chunk >> 3;
                int c4 = chunk & 7;
                cp16(sA[s] + (r * AS_STRIDE + c4 * 4) * 4,
                     &A[(size_t)(row0 + r) * 128 + k0 + c4 * 4]);
            }
        } else {
            // pooled half: gather from g_MAX, sum over planes, round, STS
#pragma unroll
            for (int i = 0; i < 2; i++) {
                int chunk = i * 512 + tid;
                int r  = chunk >> 3;
                int c4 = chunk & 7;
                int t  = row0 + r;
                int b  = t >> 15;
                int ch = (k0 - 128) + c4 * 4;
                float4 sv; sv.x = 0.0f; sv.y = 0.0f; sv.z = 0.0f; sv.w = 0.0f;
#pragma unroll
                for (int pl = 0; pl < 3; pl++) {
                    int cell = g_IDX[pl * BT + t];
                    uint4 m = *(const uint4*)&g_MAX[(size_t)((pl * BB + b) * RR2 + cell) * 128 + ch];
                    sv.x += o2f(m.x); sv.y += o2f(m.y);
                    sv.z += o2f(m.z); sv.w += o2f(m.w);
                }
                sv.x = rnd_tf32(sv.x); sv.y = rnd_tf32(sv.y);
                sv.z = rnd_tf32(sv.z); sv.w = rnd_tf32(sv.w);
                *(float4*)&AsB[s][r * AS_STRIDE + c4 * 4] = sv;
            }
        }
#pragma unroll
        for (int i = 0; i < 4; i++) {          // B tile 32x256
            int chunk = i * 512 + tid;
            int kr  = chunk >> 6;
            int nc4 = chunk & 63;
            cp16(sB[s] + (kr * B12_STRIDE + nc4 * 4) * 4,
                 &WC[(size_t)(k0 + kr) * 256 + nc4 * 4]);
        }
        cp_commit();
    };

    prefetch(0, 0);
#pragma unroll
    for (int kt = 0; kt < 8; kt++) {
        int cur = kt & 1;
        cp_wait0();
        __syncthreads();
        if (kt + 1 < 8) prefetch((kt + 1) * 32, cur ^ 1);

        const float* as = AsB[cur];
        const float* bs = BsB[cur];
#pragma unroll
        for (int kk = 0; kk < 32; kk += 8) {
            uint32_t af[2][4];
#pragma unroll
            for (int mf = 0; mf < 2; mf++) {
                int r = wm + mf * 16;
                float a0 = as[(r + gid    ) * AS_STRIDE + kk + tig    ];
                float a1 = as[(r + gid + 8) * AS_STRIDE + kk + tig    ];
                float a2 = as[(r + gid    ) * AS_STRIDE + kk + tig + 4];
                float a3 = as[(r + gid + 8) * AS_STRIDE + kk + tig + 4];
                if (hpath) {
                    a0 = fmaxf(a0, 0.0f); a1 = fmaxf(a1, 0.0f);
                    a2 = fmaxf(a2, 0.0f); a3 = fmaxf(a3, 0.0f);
                }
                af[mf][0] = __float_as_uint(a0);
                af[mf][1] = __float_as_uint(a1);
                af[mf][2] = __float_as_uint(a2);
                af[mf][3] = __float_as_uint(a3);
            }
            uint32_t bf[8][2];
#pragma unroll
            for (int nf = 0; nf < 8; nf++) {
                bf[nf][0] = __float_as_uint(bs[(kk + tig    ) * B12_STRIDE + wn + nf * 8 + gid]);
                bf[nf][1] = __float_as_uint(bs[(kk + tig + 4) * B12_STRIDE + wn + nf * 8 + gid]);
            }
#pragma unroll
            for (int mf = 0; mf < 2; mf++)
#pragma unroll
                for (int nf = 0; nf < 8; nf++)
                    mma_tf32(acc[mf][nf], af[mf], bf[nf]);
        }
        __syncthreads();
    }

    // epilogue: cols <128 -> H (bias+relu+cvt); cols >=128 -> NT (raw fp32)
#pragma unroll
    for (int mf = 0; mf < 2; mf++) {
        int r0 = row0 + wm + mf * 16 + gid;
#pragma unroll
        for (int nf = 0; nf < 8; nf++) {
            int c = wn + nf * 8 + 2 * tig;
            float v0 = acc[mf][nf][0], v1 = acc[mf][nf][1];
            float v2 = acc[mf][nf][2], v3 = acc[mf][nf][3];
            if (hpath) {
                float bb0 = b0[c], bb1 = b0[c + 1];
                v0 = rnd_tf32(fmaxf(v0 + bb0, 0.0f));
                v1 = rnd_tf32(fmaxf(v1 + bb1, 0.0f));
                v2 = rnd_tf32(fmaxf(v2 + bb0, 0.0f));
                v3 = rnd_tf32(fmaxf(v3 + bb1, 0.0f));
                float2 s0; s0.x = v0; s0.y = v1;
                float2 s1; s1.x = v2; s1.y = v3;
                *(float2*)&Hout[(size_t)r0 * 128 + c] = s0;
                *(float2*)&Hout[(size_t)(r0 + 8) * 128 + c] = s1;
            } else {
                int cn = c - 128;
                float2 s0; s0.x = v0; s0.y = v1;
                float2 s1; s1.x = v2; s1.y = v3;
                *(float2*)&NTout[(size_t)r0 * 128 + cn] = s0;
                *(float2*)&NTout[(size_t)(r0 + 8) * 128 + cn] = s1;
            }
        }
    }
}

// ================= generic 256-thread GEMM (G3 with fused scatter, FC) =================
#define BS_STRIDE 136
#define BS_FLOATS (32*BS_STRIDE)    // 4352
#define SMEM_BYTES ((2*AS_FLOATS + 2*BS_FLOATS) * 4)   // 71680

template<int K, bool BIAS, bool ACCD, bool OCVT, bool SCAT>
__global__ void __launch_bounds__(256, 2)
k_tgemm(const float* __restrict__ A, int ASt,
        const float* __restrict__ W, int Nout,
        const float* __restrict__ bias,
        const float* __restrict__ D, int DS,
        float* __restrict__ Cm, int CS) {
    extern __shared__ float smem[];
    float* AsB[2] = { smem, smem + AS_FLOATS };
    float* BsB[2] = { smem + 2*AS_FLOATS, smem + 2*AS_FLOATS + BS_FLOATS };

    int tid  = threadIdx.x;
    int wid  = tid >> 5, lane = tid & 31;
    int gid  = lane >> 2, tig = lane & 3;
    int wm   = (wid >> 1) * 32;
    int wn   = (wid & 1) * 64;
    int row0 = blockIdx.y * 128;
    int col0 = blockIdx.x * 128;

    uint32_t sA[2], sB[2];
    sA[0] = (uint32_t)__cvta_generic_to_shared(AsB[0]);
    sA[1] = (uint32_t)__cvta_generic_to_shared(AsB[1]);
    sB[0] = (uint32_t)__cvta_generic_to_shared(BsB[0]);
    sB[1] = (uint32_t)__cvta_generic_to_shared(BsB[1]);

    float acc[2][8][4];
#pragma unroll
    for (int mf = 0; mf < 2; mf++)
#pragma unroll
        for (int nf = 0; nf < 8; nf++)
#pragma unroll
            for (int i = 0; i < 4; i++) acc[mf][nf][i] = 0.0f;

    auto prefetch = [&](int k0, int s) {
#pragma unroll
        for (int i = 0; i < 4; i++) {
            int chunk = i * 256 + tid;
            int r  = chunk >> 3;
            int c4 = chunk & 7;
            cp16(sA[s] + (r * AS_STRIDE + c4 * 4) * 4,
                 &A[(size_t)(row0 + r) * ASt + k0 + c4 * 4]);
        }
#pragma unroll
        for (int i = 0; i < 4; i++) {
            int chunk = i * 256 + tid;
            int kr  = chunk >> 5;
            int nc4 = chunk & 31;
            cp16(sB[s] + (kr * BS_STRIDE + nc4 * 4) * 4,
                 &W[(size_t)(k0 + kr) * Nout + col0 + nc4 * 4]);
        }
        cp_commit();
    };

    constexpr int NK = K / 32;
    prefetch(0, 0);

#pragma unroll
    for (int kt = 0; kt < NK; kt++) {
        int cur = kt & 1;
        cp_wait0();
        __syncthreads();
        if (kt + 1 < NK) prefetch((kt + 1) * 32, cur ^ 1);

        const float* as = AsB[cur];
        const float* bs = BsB[cur];
#pragma unroll
        for (int kk = 0; kk < 32; kk += 8) {
            uint32_t af[2][4];
#pragma unroll
            for (int mf = 0; mf < 2; mf++) {
                int r = wm + mf * 16;
                af[mf][0] = __float_as_uint(as[(r + gid    ) * AS_STRIDE + kk + tig    ]);
                af[mf][1] = __float_as_uint(as[(r + gid + 8) * AS_STRIDE + kk + tig    ]);
                af[mf][2] = __float_as_uint(as[(r + gid    ) * AS_STRIDE + kk + tig + 4]);
                af[mf][3] = __float_as_uint(as[(r + gid + 8) * AS_STRIDE + kk + tig + 4]);
            }
            uint32_t bf[8][2];
#pragma unroll
            for (int nf = 0; nf < 8; nf++) {
                bf[nf][0] = __float_as_uint(bs[(kk + tig    ) * BS_STRIDE + wn + nf * 8 + gid]);
                bf[nf][1] = __float_as_uint(bs[(kk + tig + 4) * BS_STRIDE + wn + nf * 8 + gid]);
            }
#pragma unroll
            for (int mf = 0; mf < 2; mf++)
#pragma unroll
                for (int nf = 0; nf < 8; nf++)
                    mma_tf32(acc[mf][nf], af[mf], bf[nf]);
        }
        __syncthreads();
    }

    // cell indices for the 4 rows this thread writes (SCAT only)
    int cells[2][2][3];
    if (SCAT) {
#pragma unroll
        for (int mf = 0; mf < 2; mf++) {
            int r0 = row0 + wm + mf * 16 + gid;
#pragma unroll
            for (int pl = 0; pl < 3; pl++) {
                cells[mf][0][pl] = g_IDX[pl * BT + r0];
                cells[mf][1][pl] = g_IDX[pl * BT + r0 + 8];
            }
        }
    }

#pragma unroll
    for (int mf = 0; mf < 2; mf++) {
        int r0 = row0 + wm + mf * 16 + gid;
        int b0r = r0 >> 15, b1r = (r0 + 8) >> 15;
#pragma unroll
        for (int nf = 0; nf < 8; nf++) {
            int c = col0 + wn + nf * 8 + 2 * tig;
            float v0 = acc[mf][nf][0], v1 = acc[mf][nf][1];
            float v2 = acc[mf][nf][2], v3 = acc[mf][nf][3];
            if (BIAS) {
                float b0 = bias[c], b1 = bias[c + 1];
                v0 += b0; v1 += b1; v2 += b0; v3 += b1;
            }
            if (ACCD) {
                float2 d0 = *(const float2*)&D[(size_t)r0 * DS + c];
                float2 d1 = *(const float2*)&D[(size_t)(r0 + 8) * DS + c];
                v0 += d0.x; v1 += d0.y; v2 += d1.x; v3 += d1.y;
            }
            if (OCVT) {
                v0 = rnd_tf32(v0); v1 = rnd_tf32(v1);
                v2 = rnd_tf32(v2); v3 = rnd_tf32(v3);
            }
            float2 s0; s0.x = v0; s0.y = v1;
            float2 s1; s1.x = v2; s1.y = v3;
            *(float2*)&Cm[(size_t)r0 * CS + c] = s0;
            *(float2*)&Cm[(size_t)(r0 + 8) * CS + c] = s1;
            if (SCAT) {
                unsigned o0 = f2o(v0), o1 = f2o(v1), o2 = f2o(v2), o3 = f2o(v3);
#pragma unroll
                for (int pl = 0; pl < 3; pl++) {
                    unsigned* m0 = &g_MAX[(size_t)((pl * BB + b0r) * RR2 + cells[mf][0][pl]) * 128 + c];
                    unsigned* m1 = &g_MAX[(size_t)((pl * BB + b1r) * RR2 + cells[mf][1][pl]) * 128 + c];
                    redmax_u32(m0,     o0); redmax_u32(m0 + 1, o1);
                    redmax_u32(m1,     o2); redmax_u32(m1 + 1, o3);
                }
            }
        }
    }
}

// ---------------- zeroing ----------------
__global__ void k_zero_u(unsigned* ptr, int n) {
    for (int i = blockIdx.x * 256 + threadIdx.x; i < n; i += gridDim.x * 256) ptr[i] = 0u;
}
__global__ void k_zero_f(float* ptr, int n) {
    for (int i = blockIdx.x * 256 + threadIdx.x; i < n; i += gridDim.x * 256) ptr[i] = 0.0f;
}

// ---------------- scatter mean: pre-scaled adds (FEA holds means) ----------------
__global__ void k_scatter_add() {
    int gi = blockIdx.x * 256 + threadIdx.x;   // BT*128 threads
    int t = gi >> 7, c4 = (gi & 127) * 4;
    int b = t >> 15;
    float4 v = *(const float4*)&g_C[(size_t)t * CDIM + c4];
#pragma unroll
    for (int pl = 0; pl < 3; pl++) {
        int cell = g_IDX[pl * BT + t];
        float inv = g_INV[(pl * BB + b) * RR2 + cell];
        float* f = &g_FEA[(size_t)((pl * BB + b) * RR2 + cell) * CDIM + c4];
        asm volatile("red.global.add.v4.f32 [%0], {%1, %2, %3, %4};"
                     :: "l"(f), "f"(v.x * inv), "f"(v.y * inv),
                        "f"(v.z * inv), "f"(v.w * inv) : "memory");
    }
}

// ---------------- bilinear sample + sum over planes ----------------
__device__ __forceinline__ float4 samp4(int pl, float u, float v, int b, int c4) {
    float nu = nrmc(u), nv = nrmc(v);
    float gx = nu * (RR - 1), gy = nv * (RR - 1);
    float x0f = floorf(gx), y0f = floorf(gy);
    float wx = gx - x0f, wy = gy - y0f;
    int x0 = min(max((int)x0f, 0), RR - 1);
    int x1 = min(x0 + 1, RR - 1);
    int y0 = min(max((int)y0f, 0), RR - 1);
    int y1 = min(y0 + 1, RR - 1);
    const float* f = g_FEA + (size_t)((pl * BB + b) * RR2) * CDIM + c4;
    float4 f00 = *(const float4*)&f[(y0 * RR + x0) * CDIM];
    float4 f01 = *(const float4*)&f[(y0 * RR + x1) * CDIM];
    float4 f10 = *(const float4*)&f[(y1 * RR + x0) * CDIM];
    float4 f11 = *(const float4*)&f[(y1 * RR + x1) * CDIM];
    float w00 = (1.0f - wx) * (1.0f - wy), w01 = wx * (1.0f - wy);
    float w10 = (1.0f - wx) * wy,          w11 = wx * wy;
    float4 r;
    r.x = f00.x * w00 + f01.x * w01 + f10.x * w10 + f11.x * w11;
    r.y = f00.y * w00 + f01.y * w01 + f10.y * w10 + f11.y * w11;
    r.z = f00.z * w00 + f01.z * w01 + f10.z * w10 + f11.z * w11;
    r.w = f00.w * w00 + f01.w * w01 + f10.w * w10 + f11.w * w11;
    return r;
}

__global__ void k_sample(const float* __restrict__ query, float* __restrict__ out) {
    int gi = blockIdx.x * 256 + threadIdx.x;   // BB*QQ*128 threads
    int c4 = (gi & 127) * 4;
    int q  = gi >> 7;
    int b  = q >> 13;
    float qx = query[q*3+0], qy = query[q*3+1], qz = query[q*3+2];
    float4 a = samp4(0, qx, qz, b, c4);
    float4 s1 = samp4(1, qx, qy, b, c4);
    float4 s2 = samp4(2, qy, qz, b, c4);
    a.x += s1.x + s2.x; a.y += s1.y + s2.y;
    a.z += s1.z + s2.z; a.w += s1.w + s2.w;
    *(float4*)&out[(size_t)q * CDIM + c4] = a;
}

// ---------------- launch ----------------
extern "C" void kernel_launch(void* const* d_in, const int* in_sizes, int n_in,
                              void* d_out, int out_size) {
    const float* p        = (const float*)d_in[0];
    const float* query    = (const float*)d_in[1];
    const float* fc_pos_w = (const float*)d_in[2];
    const float* fc_pos_b = (const float*)d_in[3];
    const float* blk_w0   = (const float*)d_in[4];
    const float* blk_b0   = (const float*)d_in[5];
    const float* blk_w1   = (const float*)d_in[6];
    const float* blk_b1   = (const float*)d_in[7];
    const float* blk_ws   = (const float*)d_in[8];
    const float* fc_c_w   = (const float*)d_in[9];
    const float* fc_c_b   = (const float*)d_in[10];
    float* out = (float*)d_out;

    float *X, *NET, *H, *NT, *Cb, *FEA, *CNT, *WP;
    unsigned* MAXB;
    cudaGetSymbolAddress((void**)&X,    g_X);
    cudaGetSymbolAddress((void**)&NET,  g_NET);
    cudaGetSymbolAddress((void**)&H,    g_H);
    cudaGetSymbolAddress((void**)&NT,   g_NT);
    cudaGetSymbolAddress((void**)&Cb,   g_C);
    cudaGetSymbolAddress((void**)&FEA,  g_FEA);
    cudaGetSymbolAddress((void**)&CNT,  g_CNT);
    cudaGetSymbolAddress((void**)&WP,   g_WP);
    cudaGetSymbolAddress((void**)&MAXB, g_MAX);

    cudaFuncSetAttribute(k_tgemm12<false>, cudaFuncAttributeMaxDynamicSharedMemorySize, SMEM12);
    cudaFuncSetAttribute(k_tgemm12<true >, cudaFuncAttributeMaxDynamicSharedMemorySize, SMEM12);
    cudaFuncSetAttribute(k_tgemm<128, true, true,  true,  true >, cudaFuncAttributeMaxDynamicSharedMemorySize, SMEM_BYTES);
    cudaFuncSetAttribute(k_tgemm<128, true, true,  true,  false>, cudaFuncAttributeMaxDynamicSharedMemorySize, SMEM_BYTES);
    cudaFuncSetAttribute(k_tgemm<128, true, false, false, false>, cudaFuncAttributeMaxDynamicSharedMemorySize, SMEM_BYTES);

    k_cvtw_all<<<(475136 + 255) / 256, 256>>>(blk_w0, blk_w1, blk_ws, fc_c_w, WP);
    k_zero_f<<<48, 256>>>(CNT, 3*BB*RR2);
    k_index<<<BT/256, 256>>>(p);
    k_inv<<<(3*BB*RR2 + 255)/256, 256>>>();
    k_pos<<<BT, 256>>>(p, fc_pos_w, fc_pos_b);

    dim3 g12(1, BT/128);
    dim3 g128(1, BT/128);
    dim3 g512(4, BT/128);

    for (int i = 0; i < 5; i++) {
        const float* wc = WP + WP_WC + i*256*256;
        const float* b0 = blk_b0 + i*128;
        const float* w1 = WP + WP_W1 + i*128*128;
        const float* b1 = blk_b1 + i*128;
        // fused G1+G2 (reads MAX built by previous iteration's G3 when i>0)
        if (i == 0)
            k_tgemm12<false><<<g12, 512, SMEM12>>>(X, wc, b0, H, NT);
        else
            k_tgemm12<true ><<<g12, 512, SMEM12>>>(NET, wc, b0, H, NT);
        // G3: NET = cvt(H@w1 + b1 + NT); i<4 also scatter-max into fresh MAX
        if (i < 4) {
            k_zero_u<<<2048, 256>>>(MAXB, 3*BB*RR2*128);
            k_tgemm<128, true, true, true, true ><<<g128, 256, SMEM_BYTES>>>(H, 128, w1, 128, b1, NT, 128, NET, 128);
        } else {
            k_tgemm<128, true, true, true, false><<<g128, 256, SMEM_BYTES>>>(H, 128, w1, 128, b1, NT, 128, NET, 128);
        }
    }

    // c = NET @ fc_c_w + fc_c_b
    k_tgemm<128, true, false, false, false><<<g512, 256, SMEM_BYTES>>>(NET, 128, WP + WP_FC, 512, fc_c_b, nullptr, 0, Cb, 512);

    // scatter mean into plane grids (pre-scaled adds; FEA = means)
    k_zero_f<<<4096, 256>>>(FEA, 3*BB*RR2*CDIM);
    k_scatter_add<<<BT*128/256, 256>>>();

    // bilinear sample queries
    k_sample<<<BB*QQ*128/256, 256>>>(query, out);
}

// round 9
// speedup vs baseline: 1.2080x; 1.0507x over previous
#include <cuda_runtime.h>
#include <math.h>
#include <stdint.h>

#define BB   4
#define TT   32768
#define BT   (BB*TT)           // 131072 points
#define QQ   8192
#define HH   128
#define RR   64
#define RR2  4096
#define CDIM 512

// ---------------- scratch (static device memory; no allocations) ----------------
__device__ float    g_NET[BT*128];            // block output NET (tf32-rounded), stride 128
__device__ float    g_H  [BT*128];            // hidden (relu'd + tf32-rounded)
__device__ float    g_NT [BT*128];            // shortcut temp (fp32)
__device__ unsigned g_MAX[3*BB*RR2*128];      // per-plane max pool
__device__ float    g_FEA[3*BB*RR2*CDIM];     // per-plane mean feat
__device__ float    g_CNT[3*BB*RR2];          // per-plane counts
__device__ float    g_INV[3*BB*RR2];          // per-plane 1/max(count,1)
__device__ int      g_IDX[3*BT];              // per-plane cell index
__device__ float    g_WP [475136];            // tf32 weights: WC | W1 | FC

#define WP_WC 0                               // 5*256*256 = 327680 ([w0|ws] concat)
#define WP_W1 327680                          // 5*128*128 =  81920
#define WP_FC 409600                          // 128*512   =  65536

// ---------------- helpers ----------------
__device__ __forceinline__ unsigned f2o(float f) {
    unsigned b = __float_as_uint(f);
    return (b & 0x80000000u) ? ~b : (b | 0x80000000u);
}
__device__ __forceinline__ float o2f(unsigned o) {
    return __uint_as_float((o & 0x80000000u) ? (o ^ 0x80000000u) : ~o);
}
__device__ __forceinline__ float nrmc(float v) {
    v = v * (1.0f / 1.1f) + 0.5f;
    return fminf(fmaxf(v, 0.0f), 1.0f - 1e-6f);
}
__device__ __forceinline__ uint32_t to_tf32(float x) {
    uint32_t u;
    asm("cvt.rna.tf32.f32 %0, %1;" : "=r"(u) : "f"(x));
    return u;
}
__device__ __forceinline__ float rnd_tf32(float x) {
    return __uint_as_float(to_tf32(x));
}
__device__ __forceinline__ void mma_tf32(float c[4], const uint32_t a[4], const uint32_t b[2]) {
    asm volatile(
        "mma.sync.aligned.m16n8k8.row.col.f32.tf32.tf32.f32 "
        "{%0,%1,%2,%3}, {%4,%5,%6,%7}, {%8,%9}, {%0,%1,%2,%3};"
        : "+f"(c[0]), "+f"(c[1]), "+f"(c[2]), "+f"(c[3])
        : "r"(a[0]), "r"(a[1]), "r"(a[2]), "r"(a[3]), "r"(b[0]), "r"(b[1]));
}
__device__ __forceinline__ void cp16(uint32_t s, const float* g) {
    asm volatile("cp.async.cg.shared.global [%0], [%1], 16;" :: "r"(s), "l"(g));
}
__device__ __forceinline__ void cp_commit() { asm volatile("cp.async.commit_group;"); }
__device__ __forceinline__ void cp_wait0()  { asm volatile("cp.async.wait_group 0;"); }
__device__ __forceinline__ void redmax_u32(unsigned* p, unsigned v) {
    asm volatile("red.global.max.u32 [%0], %1;" :: "l"(p), "r"(v) : "memory");
}
__device__ __forceinline__ void redadd2(float* p, float a, float b) {
    asm volatile("red.global.add.v2.f32 [%0], {%1, %2};" :: "l"(p), "f"(a), "f"(b) : "memory");
}

// ---------------- weight prep: tf32 round, build WC=[w0|ws] concat ----------------
__global__ void k_cvtw_all(const float* __restrict__ w0, const float* __restrict__ w1,
                           const float* __restrict__ ws, const float* __restrict__ fc,
                           float* __restrict__ WP) {
    int i = blockIdx.x * 256 + threadIdx.x;
    if (i < 327680) {                 // WC: blk 5 x (256k x 256n)
        int blk = i >> 16, rem = i & 65535;
        int k = rem >> 8, n = rem & 255;
        float v = (n < 128) ? w0[blk*32768 + k*128 + n]
                            : ws[blk*32768 + k*128 + (n - 128)];
        WP[i] = rnd_tf32(v);
    } else if (i < 409600) {          // W1
        WP[i] = rnd_tf32(w1[i - 327680]);
    } else if (i < 475136) {          // FC
        WP[i] = rnd_tf32(fc[i - 409600]);
    }
}

// ---------------- index computation + counts ----------------
__global__ void k_index(const float* __restrict__ p) {
    int t = blockIdx.x * 256 + threadIdx.x;
    if (t >= BT) return;
    float x = p[t*3+0], y = p[t*3+1], z = p[t*3+2];
    int b = t >> 15;
    int gx, gy, cell;
    gx = (int)floorf(nrmc(x) * RR); gy = (int)floorf(nrmc(z) * RR);
    cell = gx + RR*gy; g_IDX[0*BT + t] = cell;
    atomicAdd(&g_CNT[(0*BB + b)*RR2 + cell], 1.0f);
    gx = (int)floorf(nrmc(x) * RR); gy = (int)floorf(nrmc(y) * RR);
    cell = gx + RR*gy; g_IDX[1*BT + t] = cell;
    atomicAdd(&g_CNT[(1*BB + b)*RR2 + cell], 1.0f);
    gx = (int)floorf(nrmc(y) * RR); gy = (int)floorf(nrmc(z) * RR);
    cell = gx + RR*gy; g_IDX[2*BT + t] = cell;
    atomicAdd(&g_CNT[(2*BB + b)*RR2 + cell], 1.0f);
}

// ---------------- inverse counts ----------------
__global__ void k_inv() {
    int i = blockIdx.x * 256 + threadIdx.x;
    if (i < 3*BB*RR2) g_INV[i] = 1.0f / fmaxf(g_CNT[i], 1.0f);
}

// ================= fused G1+G2 =================
// MODE 0 (POS):    A tile computed on the fly: X0 = rnd(p @ fc_pos_w + fc_pos_b)
// MODE 1 (POOLED): A = [NET | pooled-from-MAX]
// H = cvt(relu(relu(A)@w0 + b0)); NT = A@ws.
// 512 threads, 16 warps (4m x 4n), warp tile 32x64, k-chunk 32, 2-stage cp.async.
#define AS_STRIDE   36
#define AS_FLOATS   (128*AS_STRIDE)            // 4608
#define B12_STRIDE  264
#define B12_FLOATS  (32*B12_STRIDE)            // 8448
#define SMEM12      ((2*AS_FLOATS + 2*B12_FLOATS) * 4)   // 104448 bytes

template<int MODE>
__global__ void __launch_bounds__(512, 1)
k_tgemm12(const float* __restrict__ A,          // NET (stride 128), unused in MODE 0
          const float* __restrict__ P,          // points (MODE 0)
          const float* __restrict__ PW,         // fc_pos_w (MODE 0)
          const float* __restrict__ PB,         // fc_pos_b (MODE 0)
          const float* __restrict__ WC,         // 256x256 concat, tf32
          const float* __restrict__ b0,
          float* __restrict__ Hout,             // stride 128
          float* __restrict__ NTout) {          // stride 128
    extern __shared__ float smem[];
    float* AsB[2] = { smem, smem + AS_FLOATS };
    float* BsB[2] = { smem + 2*AS_FLOATS, smem + 2*AS_FLOATS + B12_FLOATS };

    int tid  = threadIdx.x;
    int wid  = tid >> 5, lane = tid & 31;
    int gid  = lane >> 2, tig = lane & 3;
    int wm   = (wid >> 2) * 32;
    int wn   = (wid & 3) * 64;
    bool hpath = (wn < 128);
    int row0 = blockIdx.y * 128;

    uint32_t sA[2], sB[2];
    sA[0] = (uint32_t)__cvta_generic_to_shared(AsB[0]);
    sA[1] = (uint32_t)__cvta_generic_to_shared(AsB[1]);
    sB[0] = (uint32_t)__cvta_generic_to_shared(BsB[0]);
    sB[1] = (uint32_t)__cvta_generic_to_shared(BsB[1]);

    float acc[2][8][4];
#pragma unroll
    for (int mf = 0; mf < 2; mf++)
#pragma unroll
        for (int nf = 0; nf < 8; nf++)
#pragma unroll
            for (int i = 0; i < 4; i++) acc[mf][nf][i] = 0.0f;

    auto prefetch = [&](int k0, int s) {
        if (MODE == 0) {
            // compute X0 tile: cols k0..k0+31 of rnd(p @ PW + PB)
#pragma unroll
            for (int i = 0; i < 2; i++) {
                int chunk = i * 512 + tid;
                int r  = chunk >> 3;
                int c4 = chunk & 7;
                int t  = row0 + r;
                float p0 = P[t*3+0], p1 = P[t*3+1], p2 = P[t*3+2];
                int j = k0 + c4 * 4;
                float4 sv;
                sv.x = rnd_tf32(p0 * PW[j+0] + p1 * PW[256+j+0] + p2 * PW[512+j+0] + PB[j+0]);
                sv.y = rnd_tf32(p0 * PW[j+1] + p1 * PW[256+j+1] + p2 * PW[512+j+1] + PB[j+1]);
                sv.z = rnd_tf32(p0 * PW[j+2] + p1 * PW[256+j+2] + p2 * PW[512+j+2] + PB[j+2]);
                sv.w = rnd_tf32(p0 * PW[j+3] + p1 * PW[256+j+3] + p2 * PW[512+j+3] + PB[j+3]);
                *(float4*)&AsB[s][r * AS_STRIDE + c4 * 4] = sv;
            }
        } else if (k0 < 128) {
#pragma unroll
            for (int i = 0; i < 2; i++) {      // A tile from NET (stride 128)
                int chunk = i * 512 + tid;
                int r  = chunk >> 3;
                int c4 = chunk & 7;
                cp16(sA[s] + (r * AS_STRIDE + c4 * 4) * 4,
                     &A[(size_t)(row0 + r) * 128 + k0 + c4 * 4]);
            }
        } else {
            // pooled half: gather from g_MAX, sum over planes, round, STS
#pragma unroll
            for (int i = 0; i < 2; i++) {
                int chunk = i * 512 + tid;
                int r  = chunk >> 3;
                int c4 = chunk & 7;
                int t  = row0 + r;
                int b  = t >> 15;
                int ch = (k0 - 128) + c4 * 4;
                float4 sv; sv.x = 0.0f; sv.y = 0.0f; sv.z = 0.0f; sv.w = 0.0f;
#pragma unroll
                for (int pl = 0; pl < 3; pl++) {
                    int cell = g_IDX[pl * BT + t];
                    uint4 m = *(const uint4*)&g_MAX[(size_t)((pl * BB + b) * RR2 + cell) * 128 + ch];
                    sv.x += o2f(m.x); sv.y += o2f(m.y);
                    sv.z += o2f(m.z); sv.w += o2f(m.w);
                }
                sv.x = rnd_tf32(sv.x); sv.y = rnd_tf32(sv.y);
                sv.z = rnd_tf32(sv.z); sv.w = rnd_tf32(sv.w);
                *(float4*)&AsB[s][r * AS_STRIDE + c4 * 4] = sv;
            }
        }
#pragma unroll
        for (int i = 0; i < 4; i++) {          // B tile 32x256
            int chunk = i * 512 + tid;
            int kr  = chunk >> 6;
            int nc4 = chunk & 63;
            cp16(sB[s] + (kr * B12_STRIDE + nc4 * 4) * 4,
                 &WC[(size_t)(k0 + kr) * 256 + nc4 * 4]);
        }
        cp_commit();
    };

    prefetch(0, 0);
#pragma unroll
    for (int kt = 0; kt < 8; kt++) {
        int cur = kt & 1;
        cp_wait0();
        __syncthreads();
        if (kt + 1 < 8) prefetch((kt + 1) * 32, cur ^ 1);

        const float* as = AsB[cur];
        const float* bs = BsB[cur];
#pragma unroll
        for (int kk = 0; kk < 32; kk += 8) {
            uint32_t af[2][4];
#pragma unroll
            for (int mf = 0; mf < 2; mf++) {
                int r = wm + mf * 16;
                float a0 = as[(r + gid    ) * AS_STRIDE + kk + tig    ];
                float a1 = as[(r + gid + 8) * AS_STRIDE + kk + tig    ];
                float a2 = as[(r + gid    ) * AS_STRIDE + kk + tig + 4];
                float a3 = as[(r + gid + 8) * AS_STRIDE + kk + tig + 4];
                if (hpath) {
                    a0 = fmaxf(a0, 0.0f); a1 = fmaxf(a1, 0.0f);
                    a2 = fmaxf(a2, 0.0f); a3 = fmaxf(a3, 0.0f);
                }
                af[mf][0] = __float_as_uint(a0);
                af[mf][1] = __float_as_uint(a1);
                af[mf][2] = __float_as_uint(a2);
                af[mf][3] = __float_as_uint(a3);
            }
            uint32_t bf[8][2];
#pragma unroll
            for (int nf = 0; nf < 8; nf++) {
                bf[nf][0] = __float_as_uint(bs[(kk + tig    ) * B12_STRIDE + wn + nf * 8 + gid]);
                bf[nf][1] = __float_as_uint(bs[(kk + tig + 4) * B12_STRIDE + wn + nf * 8 + gid]);
            }
#pragma unroll
            for (int mf = 0; mf < 2; mf++)
#pragma unroll
                for (int nf = 0; nf < 8; nf++)
                    mma_tf32(acc[mf][nf], af[mf], bf[nf]);
        }
        __syncthreads();
    }

    // epilogue: cols <128 -> H (bias+relu+cvt); cols >=128 -> NT (raw fp32)
#pragma unroll
    for (int mf = 0; mf < 2; mf++) {
        int r0 = row0 + wm + mf * 16 + gid;
#pragma unroll
        for (int nf = 0; nf < 8; nf++) {
            int c = wn + nf * 8 + 2 * tig;
            float v0 = acc[mf][nf][0], v1 = acc[mf][nf][1];
            float v2 = acc[mf][nf][2], v3 = acc[mf][nf][3];
            if (hpath) {
                float bb0 = b0[c], bb1 = b0[c + 1];
                v0 = rnd_tf32(fmaxf(v0 + bb0, 0.0f));
                v1 = rnd_tf32(fmaxf(v1 + bb1, 0.0f));
                v2 = rnd_tf32(fmaxf(v2 + bb0, 0.0f));
                v3 = rnd_tf32(fmaxf(v3 + bb1, 0.0f));
                float2 s0; s0.x = v0; s0.y = v1;
                float2 s1; s1.x = v2; s1.y = v3;
                *(float2*)&Hout[(size_t)r0 * 128 + c] = s0;
                *(float2*)&Hout[(size_t)(r0 + 8) * 128 + c] = s1;
            } else {
                int cn = c - 128;
                float2 s0; s0.x = v0; s0.y = v1;
                float2 s1; s1.x = v2; s1.y = v3;
                *(float2*)&NTout[(size_t)r0 * 128 + cn] = s0;
                *(float2*)&NTout[(size_t)(r0 + 8) * 128 + cn] = s1;
            }
        }
    }
}

// ========== generic 256-thread GEMM (G3 + fused max-scatter, FC + fused mean-scatter) ==========
#define BS_STRIDE 136
#define BS_FLOATS (32*BS_STRIDE)    // 4352
#define SMEM_BYTES ((2*AS_FLOATS + 2*BS_FLOATS) * 4)   // 71680

template<int K, bool BIAS, bool ACCD, bool OCVT, bool SCAT, bool SCATM>
__global__ void __launch_bounds__(256, 2)
k_tgemm(const float* __restrict__ A, int ASt,
        const float* __restrict__ W, int Nout,
        const float* __restrict__ bias,
        const float* __restrict__ D, int DS,
        float* __restrict__ Cm, int CS) {
    extern __shared__ float smem[];
    float* AsB[2] = { smem, smem + AS_FLOATS };
    float* BsB[2] = { smem + 2*AS_FLOATS, smem + 2*AS_FLOATS + BS_FLOATS };

    int tid  = threadIdx.x;
    int wid  = tid >> 5, lane = tid & 31;
    int gid  = lane >> 2, tig = lane & 3;
    int wm   = (wid >> 1) * 32;
    int wn   = (wid & 1) * 64;
    int row0 = blockIdx.y * 128;
    int col0 = blockIdx.x * 128;

    uint32_t sA[2], sB[2];
    sA[0] = (uint32_t)__cvta_generic_to_shared(AsB[0]);
    sA[1] = (uint32_t)__cvta_generic_to_shared(AsB[1]);
    sB[0] = (uint32_t)__cvta_generic_to_shared(BsB[0]);
    sB[1] = (uint32_t)__cvta_generic_to_shared(BsB[1]);

    float acc[2][8][4];
#pragma unroll
    for (int mf = 0; mf < 2; mf++)
#pragma unroll
        for (int nf = 0; nf < 8; nf++)
#pragma unroll
            for (int i = 0; i < 4; i++) acc[mf][nf][i] = 0.0f;

    auto prefetch = [&](int k0, int s) {
#pragma unroll
        for (int i = 0; i < 4; i++) {
            int chunk = i * 256 + tid;
            int r  = chunk >> 3;
            int c4 = chunk & 7;
            cp16(sA[s] + (r * AS_STRIDE + c4 * 4) * 4,
                 &A[(size_t)(row0 + r) * ASt + k0 + c4 * 4]);
        }
#pragma unroll
        for (int i = 0; i < 4; i++) {
            int chunk = i * 256 + tid;
            int kr  = chunk >> 5;
            int nc4 = chunk & 31;
            cp16(sB[s] + (kr * BS_STRIDE + nc4 * 4) * 4,
                 &W[(size_t)(k0 + kr) * Nout + col0 + nc4 * 4]);
        }
        cp_commit();
    };

    constexpr int NK = K / 32;
    prefetch(0, 0);

#pragma unroll
    for (int kt = 0; kt < NK; kt++) {
        int cur = kt & 1;
        cp_wait0();
        __syncthreads();
        if (kt + 1 < NK) prefetch((kt + 1) * 32, cur ^ 1);

        const float* as = AsB[cur];
        const float* bs = BsB[cur];
#pragma unroll
        for (int kk = 0; kk < 32; kk += 8) {
            uint32_t af[2][4];
#pragma unroll
            for (int mf = 0; mf < 2; mf++) {
                int r = wm + mf * 16;
                af[mf][0] = __float_as_uint(as[(r + gid    ) * AS_STRIDE + kk + tig    ]);
                af[mf][1] = __float_as_uint(as[(r + gid + 8) * AS_STRIDE + kk + tig    ]);
                af[mf][2] = __float_as_uint(as[(r + gid    ) * AS_STRIDE + kk + tig + 4]);
                af[mf][3] = __float_as_uint(as[(r + gid + 8) * AS_STRIDE + kk + tig + 4]);
            }
            uint32_t bf[8][2];
#pragma unroll
            for (int nf = 0; nf < 8; nf++) {
                bf[nf][0] = __float_as_uint(bs[(kk + tig    ) * BS_STRIDE + wn + nf * 8 + gid]);
                bf[nf][1] = __float_as_uint(bs[(kk + tig + 4) * BS_STRIDE + wn + nf * 8 + gid]);
            }
#pragma unroll
            for (int mf = 0; mf < 2; mf++)
#pragma unroll
                for (int nf = 0; nf < 8; nf++)
                    mma_tf32(acc[mf][nf], af[mf], bf[nf]);
        }
        __syncthreads();
    }

#pragma unroll
    for (int mf = 0; mf < 2; mf++) {
        int r0 = row0 + wm + mf * 16 + gid;
        int b0r = r0 >> 15, b1r = (r0 + 8) >> 15;
        int cell0[3], cell1[3];
        float iv0[3], iv1[3];
        if (SCAT || SCATM) {
#pragma unroll
            for (int pl = 0; pl < 3; pl++) {
                cell0[pl] = g_IDX[pl * BT + r0];
                cell1[pl] = g_IDX[pl * BT + r0 + 8];
                if (SCATM) {
                    iv0[pl] = g_INV[(pl * BB + b0r) * RR2 + cell0[pl]];
                    iv1[pl] = g_INV[(pl * BB + b1r) * RR2 + cell1[pl]];
                }
            }
        }
#pragma unroll
        for (int nf = 0; nf < 8; nf++) {
            int c = col0 + wn + nf * 8 + 2 * tig;
            float v0 = acc[mf][nf][0], v1 = acc[mf][nf][1];
            float v2 = acc[mf][nf][2], v3 = acc[mf][nf][3];
            if (BIAS) {
                float b0 = bias[c], b1 = bias[c + 1];
                v0 += b0; v1 += b1; v2 += b0; v3 += b1;
            }
            if (ACCD) {
                float2 d0 = *(const float2*)&D[(size_t)r0 * DS + c];
                float2 d1 = *(const float2*)&D[(size_t)(r0 + 8) * DS + c];
                v0 += d0.x; v1 += d0.y; v2 += d1.x; v3 += d1.y;
            }
            if (OCVT) {
                v0 = rnd_tf32(v0); v1 = rnd_tf32(v1);
                v2 = rnd_tf32(v2); v3 = rnd_tf32(v3);
            }
            if (!SCATM) {
                float2 s0; s0.x = v0; s0.y = v1;
                float2 s1; s1.x = v2; s1.y = v3;
                *(float2*)&Cm[(size_t)r0 * CS + c] = s0;
                *(float2*)&Cm[(size_t)(r0 + 8) * CS + c] = s1;
            }
            if (SCAT) {
                unsigned o0 = f2o(v0), o1 = f2o(v1), o2 = f2o(v2), o3 = f2o(v3);
#pragma unroll
                for (int pl = 0; pl < 3; pl++) {
                    unsigned* m0 = &g_MAX[(size_t)((pl * BB + b0r) * RR2 + cell0[pl]) * 128 + c];
                    unsigned* m1 = &g_MAX[(size_t)((pl * BB + b1r) * RR2 + cell1[pl]) * 128 + c];
                    redmax_u32(m0,     o0); redmax_u32(m0 + 1, o1);
                    redmax_u32(m1,     o2); redmax_u32(m1 + 1, o3);
                }
            }
            if (SCATM) {
#pragma unroll
                for (int pl = 0; pl < 3; pl++) {
                    float* f0 = &g_FEA[(size_t)((pl * BB + b0r) * RR2 + cell0[pl]) * CDIM + c];
                    float* f1 = &g_FEA[(size_t)((pl * BB + b1r) * RR2 + cell1[pl]) * CDIM + c];
                    redadd2(f0, v0 * iv0[pl], v1 * iv0[pl]);
                    redadd2(f1, v2 * iv1[pl], v3 * iv1[pl]);
                }
            }
        }
    }
}

// ---------------- zeroing ----------------
__global__ void k_zero_u(unsigned* ptr, int n) {
    for (int i = blockIdx.x * 256 + threadIdx.x; i < n; i += gridDim.x * 256) ptr[i] = 0u;
}
__global__ void k_zero_f(float* ptr, int n) {
    for (int i = blockIdx.x * 256 + threadIdx.x; i < n; i += gridDim.x * 256) ptr[i] = 0.0f;
}

// ---------------- bilinear sample + sum over planes ----------------
__device__ __forceinline__ float4 samp4(int pl, float u, float v, int b, int c4) {
    float nu = nrmc(u), nv = nrmc(v);
    float gx = nu * (RR - 1), gy = nv * (RR - 1);
    float x0f = floorf(gx), y0f = floorf(gy);
    float wx = gx - x0f, wy = gy - y0f;
    int x0 = min(max((int)x0f, 0), RR - 1);
    int x1 = min(x0 + 1, RR - 1);
    int y0 = min(max((int)y0f, 0), RR - 1);
    int y1 = min(y0 + 1, RR - 1);
    const float* f = g_FEA + (size_t)((pl * BB + b) * RR2) * CDIM + c4;
    float4 f00 = *(const float4*)&f[(y0 * RR + x0) * CDIM];
    float4 f01 = *(const float4*)&f[(y0 * RR + x1) * CDIM];
    float4 f10 = *(const float4*)&f[(y1 * RR + x0) * CDIM];
    float4 f11 = *(const float4*)&f[(y1 * RR + x1) * CDIM];
    float w00 = (1.0f - wx) * (1.0f - wy), w01 = wx * (1.0f - wy);
    float w10 = (1.0f - wx) * wy,          w11 = wx * wy;
    float4 r;
    r.x = f00.x * w00 + f01.x * w01 + f10.x * w10 + f11.x * w11;
    r.y = f00.y * w00 + f01.y * w01 + f10.y * w10 + f11.y * w11;
    r.z = f00.z * w00 + f01.z * w01 + f10.z * w10 + f11.z * w11;
    r.w = f00.w * w00 + f01.w * w01 + f10.w * w10 + f11.w * w11;
    return r;
}

__global__ void k_sample(const float* __restrict__ query, float* __restrict__ out) {
    int gi = blockIdx.x * 256 + threadIdx.x;   // BB*QQ*128 threads
    int c4 = (gi & 127) * 4;
    int q  = gi >> 7;
    int b  = q >> 13;
    float qx = query[q*3+0], qy = query[q*3+1], qz = query[q*3+2];
    float4 a = samp4(0, qx, qz, b, c4);
    float4 s1 = samp4(1, qx, qy, b, c4);
    float4 s2 = samp4(2, qy, qz, b, c4);
    a.x += s1.x + s2.x; a.y += s1.y + s2.y;
    a.z += s1.z + s2.z; a.w += s1.w + s2.w;
    *(float4*)&out[(size_t)q * CDIM + c4] = a;
}

// ---------------- launch ----------------
extern "C" void kernel_launch(void* const* d_in, const int* in_sizes, int n_in,
                              void* d_out, int out_size) {
    const float* p        = (const float*)d_in[0];
    const float* query    = (const float*)d_in[1];
    const float* fc_pos_w = (const float*)d_in[2];
    const float* fc_pos_b = (const float*)d_in[3];
    const float* blk_w0   = (const float*)d_in[4];
    const float* blk_b0   = (const float*)d_in[5];
    const float* blk_w1   = (const float*)d_in[6];
    const float* blk_b1   = (const float*)d_in[7];
    const float* blk_ws   = (const float*)d_in[8];
    const float* fc_c_w   = (const float*)d_in[9];
    const float* fc_c_b   = (const float*)d_in[10];
    float* out = (float*)d_out;

    float *NET, *H, *NT, *FEA, *CNT, *WP;
    unsigned* MAXB;
    cudaGetSymbolAddress((void**)&NET,  g_NET);
    cudaGetSymbolAddress((void**)&H,    g_H);
    cudaGetSymbolAddress((void**)&NT,   g_NT);
    cudaGetSymbolAddress((void**)&FEA,  g_FEA);
    cudaGetSymbolAddress((void**)&CNT,  g_CNT);
    cudaGetSymbolAddress((void**)&WP,   g_WP);
    cudaGetSymbolAddress((void**)&MAXB, g_MAX);

    cudaFuncSetAttribute(k_tgemm12<0>, cudaFuncAttributeMaxDynamicSharedMemorySize, SMEM12);
    cudaFuncSetAttribute(k_tgemm12<1>, cudaFuncAttributeMaxDynamicSharedMemorySize, SMEM12);
    cudaFuncSetAttribute(k_tgemm<128, true, true,  true,  true,  false>, cudaFuncAttributeMaxDynamicSharedMemorySize, SMEM_BYTES);
    cudaFuncSetAttribute(k_tgemm<128, true, true,  true,  false, false>, cudaFuncAttributeMaxDynamicSharedMemorySize, SMEM_BYTES);
    cudaFuncSetAttribute(k_tgemm<128, true, false, false, false, true >, cudaFuncAttributeMaxDynamicSharedMemorySize, SMEM_BYTES);

    k_cvtw_all<<<(475136 + 255) / 256, 256>>>(blk_w0, blk_w1, blk_ws, fc_c_w, WP);
    k_zero_f<<<48, 256>>>(CNT, 3*BB*RR2);
    k_index<<<BT/256, 256>>>(p);
    k_inv<<<(3*BB*RR2 + 255)/256, 256>>>();

    dim3 g12(1, BT/128);
    dim3 g128(1, BT/128);
    dim3 g512(4, BT/128);

    for (int i = 0; i < 5; i++) {
        const float* wc = WP + WP_WC + i*256*256;
        const float* b0 = blk_b0 + i*128;
        const float* w1 = WP + WP_W1 + i*128*128;
        const float* b1 = blk_b1 + i*128;
        // fused G1+G2 (i=0 computes X0 on the fly; i>0 reads NET + MAX)
        if (i == 0)
            k_tgemm12<0><<<g12, 512, SMEM12>>>(nullptr, p, fc_pos_w, fc_pos_b, wc, b0, H, NT);
        else
            k_tgemm12<1><<<g12, 512, SMEM12>>>(NET, nullptr, nullptr, nullptr, wc, b0, H, NT);
        // G3: NET = cvt(H@w1 + b1 + NT); i<4 also scatter-max into fresh MAX
        if (i < 4) {
            k_zero_u<<<2048, 256>>>(MAXB, 3*BB*RR2*128);
            k_tgemm<128, true, true, true, true,  false><<<g128, 256, SMEM_BYTES>>>(H, 128, w1, 128, b1, NT, 128, NET, 128);
        } else {
            k_tgemm<128, true, true, true, false, false><<<g128, 256, SMEM_BYTES>>>(H, 128, w1, 128, b1, NT, 128, NET, 128);
        }
    }

    // zero FEA, then FC with fused mean-scatter (no g_C materialization)
    k_zero_f<<<4096, 256>>>(FEA, 3*BB*RR2*CDIM);
    k_tgemm<128, true, false, false, false, true><<<g512, 256, SMEM_BYTES>>>(NET, 128, WP + WP_FC, 512, fc_c_b, nullptr, 0, nullptr, 0);

    // bilinear sample queries
    k_sample<<<BB*QQ*128/256, 256>>>(query, out);
}

// round 10
// speedup vs baseline: 1.2389x; 1.0255x over previous
#include <cuda_runtime.h>
#include <math.h>
#include <stdint.h>

#define BB   4
#define TT   32768
#define BT   (BB*TT)           // 131072 points
#define QQ   8192
#define RR   64
#define RR2  4096
#define CDIM 512

// ---------------- scratch (static device memory; no allocations) ----------------
__device__ float    g_NET[BT*128];            // block output NET (tf32-rounded), stride 128
__device__ unsigned g_MAXA[3*BB*RR2*128];     // max pool ping
__device__ unsigned g_MAXB[3*BB*RR2*128];     // max pool pong
__device__ float    g_FEA[3*BB*RR2*CDIM];     // per-plane mean feat
__device__ float    g_CNT[3*BB*RR2];          // per-plane counts
__device__ float    g_INV[3*BB*RR2];          // per-plane 1/max(count,1)
__device__ int      g_IDX[3*BT];              // per-plane cell index
__device__ float    g_WP [475136];            // tf32 weights: WC | W1 | FC

#define WP_WC 0                               // 5*256*256 = 327680 ([w0|ws] concat)
#define WP_W1 327680                          // 5*128*128 =  81920
#define WP_FC 409600                          // 128*512   =  65536

// ---------------- helpers ----------------
__device__ __forceinline__ unsigned f2o(float f) {
    unsigned b = __float_as_uint(f);
    return (b & 0x80000000u) ? ~b : (b | 0x80000000u);
}
__device__ __forceinline__ float o2f(unsigned o) {
    return __uint_as_float((o & 0x80000000u) ? (o ^ 0x80000000u) : ~o);
}
__device__ __forceinline__ float nrmc(float v) {
    v = v * (1.0f / 1.1f) + 0.5f;
    return fminf(fmaxf(v, 0.0f), 1.0f - 1e-6f);
}
__device__ __forceinline__ uint32_t to_tf32(float x) {
    uint32_t u;
    asm("cvt.rna.tf32.f32 %0, %1;" : "=r"(u) : "f"(x));
    return u;
}
__device__ __forceinline__ float rnd_tf32(float x) {
    return __uint_as_float(to_tf32(x));
}
__device__ __forceinline__ void mma_tf32(float c[4], const uint32_t a[4], const uint32_t b[2]) {
    asm volatile(
        "mma.sync.aligned.m16n8k8.row.col.f32.tf32.tf32.f32 "
        "{%0,%1,%2,%3}, {%4,%5,%6,%7}, {%8,%9}, {%0,%1,%2,%3};"
        : "+f"(c[0]), "+f"(c[1]), "+f"(c[2]), "+f"(c[3])
        : "r"(a[0]), "r"(a[1]), "r"(a[2]), "r"(a[3]), "r"(b[0]), "r"(b[1]));
}
__device__ __forceinline__ void cp16(uint32_t s, const float* g) {
    asm volatile("cp.async.cg.shared.global [%0], [%1], 16;" :: "r"(s), "l"(g));
}
__device__ __forceinline__ void cp_commit() { asm volatile("cp.async.commit_group;"); }
__device__ __forceinline__ void cp_wait0()  { asm volatile("cp.async.wait_group 0;"); }
__device__ __forceinline__ void redmax_u32(unsigned* p, unsigned v) {
    asm volatile("red.global.max.u32 [%0], %1;" :: "l"(p), "r"(v) : "memory");
}
__device__ __forceinline__ void redadd2(float* p, float a, float b) {
    asm volatile("red.global.add.v2.f32 [%0], {%1, %2};" :: "l"(p), "f"(a), "f"(b) : "memory");
}

// ---------------- weight prep: tf32 round, build WC=[w0|ws] concat ----------------
__global__ void k_cvtw_all(const float* __restrict__ w0, const float* __restrict__ w1,
                           const float* __restrict__ ws, const float* __restrict__ fc,
                           float* __restrict__ WP) {
    int i = blockIdx.x * 256 + threadIdx.x;
    if (i < 327680) {                 // WC: blk 5 x (256k x 256n)
        int blk = i >> 16, rem = i & 65535;
        int k = rem >> 8, n = rem & 255;
        float v = (n < 128) ? w0[blk*32768 + k*128 + n]
                            : ws[blk*32768 + k*128 + (n - 128)];
        WP[i] = rnd_tf32(v);
    } else if (i < 409600) {          // W1
        WP[i] = rnd_tf32(w1[i - 327680]);
    } else if (i < 475136) {          // FC
        WP[i] = rnd_tf32(fc[i - 409600]);
    }
}

// ---------------- index computation + counts ----------------
__global__ void k_index(const float* __restrict__ p) {
    int t = blockIdx.x * 256 + threadIdx.x;
    if (t >= BT) return;
    float x = p[t*3+0], y = p[t*3+1], z = p[t*3+2];
    int b = t >> 15;
    int gx, gy, cell;
    gx = (int)floorf(nrmc(x) * RR); gy = (int)floorf(nrmc(z) * RR);
    cell = gx + RR*gy; g_IDX[0*BT + t] = cell;
    atomicAdd(&g_CNT[(0*BB + b)*RR2 + cell], 1.0f);
    gx = (int)floorf(nrmc(x) * RR); gy = (int)floorf(nrmc(y) * RR);
    cell = gx + RR*gy; g_IDX[1*BT + t] = cell;
    atomicAdd(&g_CNT[(1*BB + b)*RR2 + cell], 1.0f);
    gx = (int)floorf(nrmc(y) * RR); gy = (int)floorf(nrmc(z) * RR);
    cell = gx + RR*gy; g_IDX[2*BT + t] = cell;
    atomicAdd(&g_CNT[(2*BB + b)*RR2 + cell], 1.0f);
}

__global__ void k_inv() {
    int i = blockIdx.x * 256 + threadIdx.x;
    if (i < 3*BB*RR2) g_INV[i] = 1.0f / fmaxf(g_CNT[i], 1.0f);
}

// ================= fully fused residual block =================
// Phase 1 (G1+G2): [H | NT] = [relu(A)@w0+b0 | A@ws] over the 128x256 concat weights,
//   A = X0-on-the-fly (MODE 0) or [NET | pooled-from-MAXr] (MODE 1). H, NT -> SMEM.
// Phase 2 (G3):   NET = cvt(H @ w1 + b1 + NT); optional scatter-max into MAXw.
// 512 threads; smem 202.75 KB (H/NT alias the dead phase-1 pipeline buffers).
#define AS_STRIDE   36
#define AS_FLOATS   (128*AS_STRIDE)            // 4608
#define B12_STRIDE  264
#define B12_FLOATS  (32*B12_STRIDE)            // 8448
#define PH1_AS0     0
#define PH1_AS1     AS_FLOATS                  // 4608
#define PH1_BS0     (2*AS_FLOATS)              // 9216
#define PH1_BS1     (2*AS_FLOATS + B12_FLOATS) // 17664 (ends 26112)
#define HS_OFF      0                          // 128*132 = 16896 (aliases PH1)
#define NTS_OFF     16896                      // 128*128 = 16384 (ends 33280)
#define W1_OFF      33280                      // 128*136 = 17408 (ends 50688)
#define SMEMBLK     (50688*4)                  // 202752 bytes

template<int MODE, bool SCAT>
__global__ void __launch_bounds__(512, 1)
k_block(const float* __restrict__ NETin,
        const float* __restrict__ P, const float* __restrict__ PW, const float* __restrict__ PB,
        const float* __restrict__ WC, const float* __restrict__ b0v,
        const float* __restrict__ W1, const float* __restrict__ b1v,
        const unsigned* __restrict__ MAXr, unsigned* __restrict__ MAXw,
        float* __restrict__ NETout) {
    extern __shared__ float smem[];
    float* AsB[2] = { smem + PH1_AS0, smem + PH1_AS1 };
    float* BsB[2] = { smem + PH1_BS0, smem + PH1_BS1 };
    float* Hs  = smem + HS_OFF;    // stride 132
    float* NTs = smem + NTS_OFF;   // stride 128
    float* W1s = smem + W1_OFF;    // stride 136

    int tid  = threadIdx.x;
    int wid  = tid >> 5, lane = tid & 31;
    int gid  = lane >> 2, tig = lane & 3;
    int wm   = (wid >> 2) * 32;      // 4 m-slots (shared by both phases)
    int wn   = (wid & 3) * 64;       // phase-1: 4 n-slots over 256
    bool hpath = (wn < 128);
    int row0 = blockIdx.y * 128;

    uint32_t sA[2], sB[2], sW1;
    sA[0] = (uint32_t)__cvta_generic_to_shared(AsB[0]);
    sA[1] = (uint32_t)__cvta_generic_to_shared(AsB[1]);
    sB[0] = (uint32_t)__cvta_generic_to_shared(BsB[0]);
    sB[1] = (uint32_t)__cvta_generic_to_shared(BsB[1]);
    sW1   = (uint32_t)__cvta_generic_to_shared(W1s);

    // --- early async load of w1 (group 0; L2-resident after first wave) ---
#pragma unroll
    for (int i = 0; i < 8; i++) {
        int chunk = i * 512 + tid;
        int kr = chunk >> 5, nc4 = chunk & 31;
        cp16(sW1 + (kr * 136 + nc4 * 4) * 4, &W1[kr * 128 + nc4 * 4]);
    }
    cp_commit();

    float acc[2][8][4];
#pragma unroll
    for (int mf = 0; mf < 2; mf++)
#pragma unroll
        for (int nf = 0; nf < 8; nf++)
#pragma unroll
            for (int i = 0; i < 4; i++) acc[mf][nf][i] = 0.0f;

    auto prefetch = [&](int k0, int s) {
        if (MODE == 0) {
#pragma unroll
            for (int i = 0; i < 2; i++) {
                int chunk = i * 512 + tid;
                int r  = chunk >> 3;
                int c4 = chunk & 7;
                int t  = row0 + r;
                float p0 = P[t*3+0], p1 = P[t*3+1], p2 = P[t*3+2];
                int j = k0 + c4 * 4;
                float4 sv;
                sv.x = rnd_tf32(p0 * PW[j+0] + p1 * PW[256+j+0] + p2 * PW[512+j+0] + PB[j+0]);
                sv.y = rnd_tf32(p0 * PW[j+1] + p1 * PW[256+j+1] + p2 * PW[512+j+1] + PB[j+1]);
                sv.z = rnd_tf32(p0 * PW[j+2] + p1 * PW[256+j+2] + p2 * PW[512+j+2] + PB[j+2]);
                sv.w = rnd_tf32(p0 * PW[j+3] + p1 * PW[256+j+3] + p2 * PW[512+j+3] + PB[j+3]);
                *(float4*)&AsB[s][r * AS_STRIDE + c4 * 4] = sv;
            }
        } else if (k0 < 128) {
#pragma unroll
            for (int i = 0; i < 2; i++) {
                int chunk = i * 512 + tid;
                int r  = chunk >> 3;
                int c4 = chunk & 7;
                cp16(sA[s] + (r * AS_STRIDE + c4 * 4) * 4,
                     &NETin[(size_t)(row0 + r) * 128 + k0 + c4 * 4]);
            }
        } else {
#pragma unroll
            for (int i = 0; i < 2; i++) {
                int chunk = i * 512 + tid;
                int r  = chunk >> 3;
                int c4 = chunk & 7;
                int t  = row0 + r;
                int b  = t >> 15;
                int ch = (k0 - 128) + c4 * 4;
                float4 sv; sv.x = 0.0f; sv.y = 0.0f; sv.z = 0.0f; sv.w = 0.0f;
#pragma unroll
                for (int pl = 0; pl < 3; pl++) {
                    int cell = g_IDX[pl * BT + t];
                    uint4 m = *(const uint4*)&MAXr[(size_t)((pl * BB + b) * RR2 + cell) * 128 + ch];
                    sv.x += o2f(m.x); sv.y += o2f(m.y);
                    sv.z += o2f(m.z); sv.w += o2f(m.w);
                }
                sv.x = rnd_tf32(sv.x); sv.y = rnd_tf32(sv.y);
                sv.z = rnd_tf32(sv.z); sv.w = rnd_tf32(sv.w);
                *(float4*)&AsB[s][r * AS_STRIDE + c4 * 4] = sv;
            }
        }
#pragma unroll
        for (int i = 0; i < 4; i++) {
            int chunk = i * 512 + tid;
            int kr  = chunk >> 6;
            int nc4 = chunk & 63;
            cp16(sB[s] + (kr * B12_STRIDE + nc4 * 4) * 4,
                 &WC[(size_t)(k0 + kr) * 256 + nc4 * 4]);
        }
        cp_commit();
    };

    // ---------------- phase 1 mainloop ----------------
    prefetch(0, 0);
#pragma unroll
    for (int kt = 0; kt < 8; kt++) {
        int cur = kt & 1;
        cp_wait0();
        __syncthreads();
        if (kt + 1 < 8) prefetch((kt + 1) * 32, cur ^ 1);

        const float* as = AsB[cur];
        const float* bs = BsB[cur];
#pragma unroll
        for (int kk = 0; kk < 32; kk += 8) {
            uint32_t af[2][4];
#pragma unroll
            for (int mf = 0; mf < 2; mf++) {
                int r = wm + mf * 16;
                float a0 = as[(r + gid    ) * AS_STRIDE + kk + tig    ];
                float a1 = as[(r + gid + 8) * AS_STRIDE + kk + tig    ];
                float a2 = as[(r + gid    ) * AS_STRIDE + kk + tig + 4];
                float a3 = as[(r + gid + 8) * AS_STRIDE + kk + tig + 4];
                if (hpath) {
                    a0 = fmaxf(a0, 0.0f); a1 = fmaxf(a1, 0.0f);
                    a2 = fmaxf(a2, 0.0f); a3 = fmaxf(a3, 0.0f);
                }
                af[mf][0] = __float_as_uint(a0);
                af[mf][1] = __float_as_uint(a1);
                af[mf][2] = __float_as_uint(a2);
                af[mf][3] = __float_as_uint(a3);
            }
            uint32_t bf[8][2];
#pragma unroll
            for (int nf = 0; nf < 8; nf++) {
                bf[nf][0] = __float_as_uint(bs[(kk + tig    ) * B12_STRIDE + wn + nf * 8 + gid]);
                bf[nf][1] = __float_as_uint(bs[(kk + tig + 4) * B12_STRIDE + wn + nf * 8 + gid]);
            }
#pragma unroll
            for (int mf = 0; mf < 2; mf++)
#pragma unroll
                for (int nf = 0; nf < 8; nf++)
                    mma_tf32(acc[mf][nf], af[mf], bf[nf]);
        }
        __syncthreads();   // after final iter: all phase-1 smem reads done
    }

    // ---------------- phase-1 epilogue: H, NT -> SMEM ----------------
#pragma unroll
    for (int mf = 0; mf < 2; mf++) {
        int rl = wm + mf * 16 + gid;
#pragma unroll
        for (int nf = 0; nf < 8; nf++) {
            int c = wn + nf * 8 + 2 * tig;
            float v0 = acc[mf][nf][0], v1 = acc[mf][nf][1];
            float v2 = acc[mf][nf][2], v3 = acc[mf][nf][3];
            if (hpath) {
                float bb0 = b0v[c], bb1 = b0v[c + 1];
                v0 = rnd_tf32(fmaxf(v0 + bb0, 0.0f));
                v1 = rnd_tf32(fmaxf(v1 + bb1, 0.0f));
                v2 = rnd_tf32(fmaxf(v2 + bb0, 0.0f));
                v3 = rnd_tf32(fmaxf(v3 + bb1, 0.0f));
                float2 s0; s0.x = v0; s0.y = v1;
                float2 s1; s1.x = v2; s1.y = v3;
                *(float2*)&Hs[rl * 132 + c] = s0;
                *(float2*)&Hs[(rl + 8) * 132 + c] = s1;
            } else {
                int cn = c - 128;
                float2 s0; s0.x = v0; s0.y = v1;
                float2 s1; s1.x = v2; s1.y = v3;
                *(float2*)&NTs[rl * 128 + cn] = s0;
                *(float2*)&NTs[(rl + 8) * 128 + cn] = s1;
            }
        }
    }
    __syncthreads();

    // ---------------- phase 2: NET = cvt(H @ w1 + b1 + NT) ----------------
    int wn2 = (wid & 3) * 32;       // 4 n-slots over 128
    float acc2[2][4][4];
#pragma unroll
    for (int mf = 0; mf < 2; mf++)
#pragma unroll
        for (int nf = 0; nf < 4; nf++)
#pragma unroll
            for (int i = 0; i < 4; i++) acc2[mf][nf][i] = 0.0f;

#pragma unroll 4
    for (int kk = 0; kk < 128; kk += 8) {
        uint32_t af[2][4];
#pragma unroll
        for (int mf = 0; mf < 2; mf++) {
            int r = wm + mf * 16;
            af[mf][0] = __float_as_uint(Hs[(r + gid    ) * 132 + kk + tig    ]);
            af[mf][1] = __float_as_uint(Hs[(r + gid + 8) * 132 + kk + tig    ]);
            af[mf][2] = __float_as_uint(Hs[(r + gid    ) * 132 + kk + tig + 4]);
            af[mf][3] = __float_as_uint(Hs[(r + gid + 8) * 132 + kk + tig + 4]);
        }
        uint32_t bf[4][2];
#pragma unroll
        for (int nf = 0; nf < 4; nf++) {
            bf[nf][0] = __float_as_uint(W1s[(kk + tig    ) * 136 + wn2 + nf * 8 + gid]);
            bf[nf][1] = __float_as_uint(W1s[(kk + tig + 4) * 136 + wn2 + nf * 8 + gid]);
        }
#pragma unroll
        for (int mf = 0; mf < 2; mf++)
#pragma unroll
            for (int nf = 0; nf < 4; nf++)
                mma_tf32(acc2[mf][nf], af[mf], bf[nf]);
    }

    // ---------------- phase-2 epilogue: NET out (+ scatter-max) ----------------
#pragma unroll
    for (int mf = 0; mf < 2; mf++) {
        int rl = wm + mf * 16 + gid;
        int r0 = row0 + rl;
        int b0r = r0 >> 15, b1r = (r0 + 8) >> 15;
        int cell0[3], cell1[3];
        if (SCAT) {
#pragma unroll
            for (int pl = 0; pl < 3; pl++) {
                cell0[pl] = g_IDX[pl * BT + r0];
                cell1[pl] = g_IDX[pl * BT + r0 + 8];
            }
        }
#pragma unroll
        for (int nf = 0; nf < 4; nf++) {
            int c = wn2 + nf * 8 + 2 * tig;
            float2 n0 = *(const float2*)&NTs[rl * 128 + c];
            float2 n1 = *(const float2*)&NTs[(rl + 8) * 128 + c];
            float bb0 = b1v[c], bb1 = b1v[c + 1];
            float v0 = rnd_tf32(acc2[mf][nf][0] + bb0 + n0.x);
            float v1 = rnd_tf32(acc2[mf][nf][1] + bb1 + n0.y);
            float v2 = rnd_tf32(acc2[mf][nf][2] + bb0 + n1.x);
            float v3 = rnd_tf32(acc2[mf][nf][3] + bb1 + n1.y);
            float2 s0; s0.x = v0; s0.y = v1;
            float2 s1; s1.x = v2; s1.y = v3;
            *(float2*)&NETout[(size_t)r0 * 128 + c] = s0;
            *(float2*)&NETout[(size_t)(r0 + 8) * 128 + c] = s1;
            if (SCAT) {
                unsigned o0 = f2o(v0), o1 = f2o(v1), o2 = f2o(v2), o3 = f2o(v3);
#pragma unroll
                for (int pl = 0; pl < 3; pl++) {
                    unsigned* m0 = &MAXw[(size_t)((pl * BB + b0r) * RR2 + cell0[pl]) * 128 + c];
                    unsigned* m1 = &MAXw[(size_t)((pl * BB + b1r) * RR2 + cell1[pl]) * 128 + c];
                    redmax_u32(m0,     o0); redmax_u32(m0 + 1, o1);
                    redmax_u32(m1,     o2); redmax_u32(m1 + 1, o3);
                }
            }
        }
    }
}

// ========== FC GEMM (K=128, N=512) with fused mean-scatter ==========
#define BS_STRIDE 136
#define BS_FLOATS (32*BS_STRIDE)    // 4352
#define SMEM_FC ((2*AS_FLOATS + 2*BS_FLOATS) * 4)   // 71680

__global__ void __launch_bounds__(256, 2)
k_fc(const float* __restrict__ A,
     const float* __restrict__ W,
     const float* __restrict__ bias) {
    extern __shared__ float smem[];
    float* AsB[2] = { smem, smem + AS_FLOATS };
    float* BsB[2] = { smem + 2*AS_FLOATS, smem + 2*AS_FLOATS + BS_FLOATS };

    int tid  = threadIdx.x;
    int wid  = tid >> 5, lane = tid & 31;
    int gid  = lane >> 2, tig = lane & 3;
    int wm   = (wid >> 1) * 32;
    int wn   = (wid & 1) * 64;
    int row0 = blockIdx.y * 128;
    int col0 = blockIdx.x * 128;

    uint32_t sA[2], sB[2];
    sA[0] = (uint32_t)__cvta_generic_to_shared(AsB[0]);
    sA[1] = (uint32_t)__cvta_generic_to_shared(AsB[1]);
    sB[0] = (uint32_t)__cvta_generic_to_shared(BsB[0]);
    sB[1] = (uint32_t)__cvta_generic_to_shared(BsB[1]);

    float acc[2][8][4];
#pragma unroll
    for (int mf = 0; mf < 2; mf++)
#pragma unroll
        for (int nf = 0; nf < 8; nf++)
#pragma unroll
            for (int i = 0; i < 4; i++) acc[mf][nf][i] = 0.0f;

    auto prefetch = [&](int k0, int s) {
#pragma unroll
        for (int i = 0; i < 4; i++) {
            int chunk = i * 256 + tid;
            int r  = chunk >> 3;
            int c4 = chunk & 7;
            cp16(sA[s] + (r * AS_STRIDE + c4 * 4) * 4,
                 &A[(size_t)(row0 + r) * 128 + k0 + c4 * 4]);
        }
#pragma unroll
        for (int i = 0; i < 4; i++) {
            int chunk = i * 256 + tid;
            int kr  = chunk >> 5;
            int nc4 = chunk & 31;
            cp16(sB[s] + (kr * BS_STRIDE + nc4 * 4) * 4,
                 &W[(size_t)(k0 + kr) * 512 + col0 + nc4 * 4]);
        }
        cp_commit();
    };

    prefetch(0, 0);
#pragma unroll
    for (int kt = 0; kt < 4; kt++) {
        int cur = kt & 1;
        cp_wait0();
        __syncthreads();
        if (kt + 1 < 4) prefetch((kt + 1) * 32, cur ^ 1);

        const float* as = AsB[cur];
        const float* bs = BsB[cur];
#pragma unroll
        for (int kk = 0; kk < 32; kk += 8) {
            uint32_t af[2][4];
#pragma unroll
            for (int mf = 0; mf < 2; mf++) {
                int r = wm + mf * 16;
                af[mf][0] = __float_as_uint(as[(r + gid    ) * AS_STRIDE + kk + tig    ]);
                af[mf][1] = __float_as_uint(as[(r + gid + 8) * AS_STRIDE + kk + tig    ]);
                af[mf][2] = __float_as_uint(as[(r + gid    ) * AS_STRIDE + kk + tig + 4]);
                af[mf][3] = __float_as_uint(as[(r + gid + 8) * AS_STRIDE + kk + tig + 4]);
            }
            uint32_t bf[8][2];
#pragma unroll
            for (int nf = 0; nf < 8; nf++) {
                bf[nf][0] = __float_as_uint(bs[(kk + tig    ) * BS_STRIDE + wn + nf * 8 + gid]);
                bf[nf][1] = __float_as_uint(bs[(kk + tig + 4) * BS_STRIDE + wn + nf * 8 + gid]);
            }
#pragma unroll
            for (int mf = 0; mf < 2; mf++)
#pragma unroll
                for (int nf = 0; nf < 8; nf++)
                    mma_tf32(acc[mf][nf], af[mf], bf[nf]);
        }
        __syncthreads();
    }

#pragma unroll
    for (int mf = 0; mf < 2; mf++) {
        int r0 = row0 + wm + mf * 16 + gid;
        int b0r = r0 >> 15, b1r = (r0 + 8) >> 15;
        int cell0[3], cell1[3];
        float iv0[3], iv1[3];
#pragma unroll
        for (int pl = 0; pl < 3; pl++) {
            cell0[pl] = g_IDX[pl * BT + r0];
            cell1[pl] = g_IDX[pl * BT + r0 + 8];
            iv0[pl] = g_INV[(pl * BB + b0r) * RR2 + cell0[pl]];
            iv1[pl] = g_INV[(pl * BB + b1r) * RR2 + cell1[pl]];
        }
#pragma unroll
        for (int nf = 0; nf < 8; nf++) {
            int c = col0 + wn + nf * 8 + 2 * tig;
            float v0 = acc[mf][nf][0] + bias[c];
            float v1 = acc[mf][nf][1] + bias[c + 1];
            float v2 = acc[mf][nf][2] + bias[c];
            float v3 = acc[mf][nf][3] + bias[c + 1];
#pragma unroll
            for (int pl = 0; pl < 3; pl++) {
                float* f0 = &g_FEA[(size_t)((pl * BB + b0r) * RR2 + cell0[pl]) * CDIM + c];
                float* f1 = &g_FEA[(size_t)((pl * BB + b1r) * RR2 + cell1[pl]) * CDIM + c];
                redadd2(f0, v0 * iv0[pl], v1 * iv0[pl]);
                redadd2(f1, v2 * iv1[pl], v3 * iv1[pl]);
            }
        }
    }
}

// ---------------- zeroing ----------------
__global__ void k_zero_u(unsigned* ptr, int n) {
    for (int i = blockIdx.x * 256 + threadIdx.x; i < n; i += gridDim.x * 256) ptr[i] = 0u;
}
__global__ void k_zero_f(float* ptr, int n) {
    for (int i = blockIdx.x * 256 + threadIdx.x; i < n; i += gridDim.x * 256) ptr[i] = 0.0f;
}

// ---------------- bilinear sample + sum over planes ----------------
__device__ __forceinline__ float4 samp4(int pl, float u, float v, int b, int c4) {
    float nu = nrmc(u), nv = nrmc(v);
    float gx = nu * (RR - 1), gy = nv * (RR - 1);
    float x0f = floorf(gx), y0f = floorf(gy);
    float wx = gx - x0f, wy = gy - y0f;
    int x0 = min(max((int)x0f, 0), RR - 1);
    int x1 = min(x0 + 1, RR - 1);
    int y0 = min(max((int)y0f, 0), RR - 1);
    int y1 = min(y0 + 1, RR - 1);
    const float* f = g_FEA + (size_t)((pl * BB + b) * RR2) * CDIM + c4;
    float4 f00 = *(const float4*)&f[(y0 * RR + x0) * CDIM];
    float4 f01 = *(const float4*)&f[(y0 * RR + x1) * CDIM];
    float4 f10 = *(const float4*)&f[(y1 * RR + x0) * CDIM];
    float4 f11 = *(const float4*)&f[(y1 * RR + x1) * CDIM];
    float w00 = (1.0f - wx) * (1.0f - wy), w01 = wx * (1.0f - wy);
    float w10 = (1.0f - wx) * wy,          w11 = wx * wy;
    float4 r;
    r.x = f00.x * w00 + f01.x * w01 + f10.x * w10 + f11.x * w11;
    r.y = f00.y * w00 + f01.y * w01 + f10.y * w10 + f11.y * w11;
    r.z = f00.z * w00 + f01.z * w01 + f10.z * w10 + f11.z * w11;
    r.w = f00.w * w00 + f01.w * w01 + f10.w * w10 + f11.w * w11;
    return r;
}

__global__ void k_sample(const float* __restrict__ query, float* __restrict__ out) {
    int gi = blockIdx.x * 256 + threadIdx.x;   // BB*QQ*128 threads
    int c4 = (gi & 127) * 4;
    int q  = gi >> 7;
    int b  = q >> 13;
    float qx = query[q*3+0], qy = query[q*3+1], qz = query[q*3+2];
    float4 a = samp4(0, qx, qz, b, c4);
    float4 s1 = samp4(1, qx, qy, b, c4);
    float4 s2 = samp4(2, qy, qz, b, c4);
    a.x += s1.x + s2.x; a.y += s1.y + s2.y;
    a.z += s1.z + s2.z; a.w += s1.w + s2.w;
    *(float4*)&out[(size_t)q * CDIM + c4] = a;
}

// ---------------- launch ----------------
extern "C" void kernel_launch(void* const* d_in, const int* in_sizes, int n_in,
                              void* d_out, int out_size) {
    const float* p        = (const float*)d_in[0];
    const float* query    = (const float*)d_in[1];
    const float* fc_pos_w = (const float*)d_in[2];
    const float* fc_pos_b = (const float*)d_in[3];
    const float* blk_w0   = (const float*)d_in[4];
    const float* blk_b0   = (const float*)d_in[5];
    const float* blk_w1   = (const float*)d_in[6];
    const float* blk_b1   = (const float*)d_in[7];
    const float* blk_ws   = (const float*)d_in[8];
    const float* fc_c_w   = (const float*)d_in[9];
    const float* fc_c_b   = (const float*)d_in[10];
    float* out = (float*)d_out;

    float *NET, *FEA, *CNT, *WP;
    unsigned *MAXBUF[2];
    cudaGetSymbolAddress((void**)&NET,        g_NET);
    cudaGetSymbolAddress((void**)&FEA,        g_FEA);
    cudaGetSymbolAddress((void**)&CNT,        g_CNT);
    cudaGetSymbolAddress((void**)&WP,         g_WP);
    cudaGetSymbolAddress((void**)&MAXBUF[0],  g_MAXA);
    cudaGetSymbolAddress((void**)&MAXBUF[1],  g_MAXB);

    cudaFuncSetAttribute(k_block<0, true >, cudaFuncAttributeMaxDynamicSharedMemorySize, SMEMBLK);
    cudaFuncSetAttribute(k_block<1, true >, cudaFuncAttributeMaxDynamicSharedMemorySize, SMEMBLK);
    cudaFuncSetAttribute(k_block<1, false>, cudaFuncAttributeMaxDynamicSharedMemorySize, SMEMBLK);
    cudaFuncSetAttribute(k_fc, cudaFuncAttributeMaxDynamicSharedMemorySize, SMEM_FC);

    k_cvtw_all<<<(475136 + 255) / 256, 256>>>(blk_w0, blk_w1, blk_ws, fc_c_w, WP);
    k_zero_f<<<48, 256>>>(CNT, 3*BB*RR2);
    k_index<<<BT/256, 256>>>(p);
    k_inv<<<(3*BB*RR2 + 255)/256, 256>>>();

    dim3 gblk(1, BT/128);
    dim3 gfc(4, BT/128);

    for (int i = 0; i < 5; i++) {
        const float* wc = WP + WP_WC + i*256*256;
        const float* b0 = blk_b0 + i*128;
        const float* w1 = WP + WP_W1 + i*128*128;
        const float* b1 = blk_b1 + i*128;
        int w = i & 1, r = w ^ 1;
        if (i < 4) k_zero_u<<<2048, 256>>>(MAXBUF[w], 3*BB*RR2*128);
        if (i == 0)
            k_block<0, true ><<<gblk, 512, SMEMBLK>>>(nullptr, p, fc_pos_w, fc_pos_b,
                                                      wc, b0, w1, b1,
                                                      nullptr, MAXBUF[0], NET);
        else if (i < 4)
            k_block<1, true ><<<gblk, 512, SMEMBLK>>>(NET, nullptr, nullptr, nullptr,
                                                      wc, b0, w1, b1,
                                                      MAXBUF[r], MAXBUF[w], NET);
        else
            k_block<1, false><<<gblk, 512, SMEMBLK>>>(NET, nullptr, nullptr, nullptr,
                                                      wc, b0, w1, b1,
                                                      MAXBUF[r], nullptr, NET);
    }

    // zero FEA, FC with fused mean-scatter, sample
    k_zero_f<<<4096, 256>>>(FEA, 3*BB*RR2*CDIM);
    k_fc<<<gfc, 256, SMEM_FC>>>(NET, WP + WP_FC, fc_c_b);
    k_sample<<<BB*QQ*128/256, 256>>>(query, out);
}